// round 13
// baseline (speedup 1.0000x reference)
#include <cuda_runtime.h>
#include <cuda_bf16.h>
#include <math.h>
#include <stdint.h>
#include <string.h>

// Problem constants (fixed by the dataset)
constexpr int NN  = 50000;   // nodes
constexpr int NP  = 50048;   // nodes padded to 128 (391 tiles)
constexpr int F   = 256;     // hidden
constexpr int Hh  = 8;       // heads
constexpr int EE  = 800000;  // edges per metapath
constexpr int PP  = 3;       // metapaths
constexpr int F1  = 128;     // MLP hidden

// ---------------- scratch (device globals; zero-initialized) ---------------
__device__ __align__(16) float g_h0 [NP * F];           // pad rows stay 0
__device__ __align__(16) float g_hall[PP * NP * F];     // layer-1 outputs (stacked)
__device__ __align__(16) float g_hp  [PP * NP * F];     // GEMM outputs (stacked)
__device__ __align__(16) float g_ssrc[PP * NP * Hh];
__device__ __align__(16) float g_sdst[PP * NP * Hh];
__device__ __align__(16) float g_emb [PP * NP * F];
__device__ __align__(16) float g_t1  [PP * NP * F1];
__device__ __align__(16) float g_sc  [NN * PP];
__device__ __align__(16) float g_z   [NN * F];
__device__ __align__(16) float g_t2  [NN * F1];

// CSR structures
__device__ int g_count [PP * NN];
__device__ int g_indptr[PP * (NN + 1)];
__device__ int g_cursor[PP * NN];
__device__ int g_csrc  [PP * EE];

// split-bf16 weights, transposed to [N][K], hi then lo per matrix
__device__ __align__(16) __nv_bfloat16 g_wt[983040];

// feature gate: tcgen05 only exists in an arch-specific (sm_103a/100a) pass
#if defined(__CUDA_ARCH_FEAT_SM103_ALL) || defined(__CUDA_ARCH_FEAT_SM100_ALL) || defined(__CUDA_ARCH_FEAT_SM101_ALL)
#define HAVE_TCGEN05 1
#else
#define HAVE_TCGEN05 0
#endif

// ---------------- PTX helpers ----------------------------------------------
__device__ __forceinline__ uint32_t elect_one_pred() {
    uint32_t pred;
    asm volatile(
        "{\n\t.reg .pred p;\n\t"
        "elect.sync _|p, 0xFFFFFFFF;\n\t"
        "selp.b32 %0, 1, 0, p;\n\t}"
        : "=r"(pred));
    return pred;
}
__device__ __forceinline__ uint32_t smem_u32(const void* p) {
    uint32_t a;
    asm("{ .reg .u64 t; cvta.to.shared.u64 t, %1; cvt.u32.u64 %0, t; }"
        : "=r"(a) : "l"(p));
    return a;
}

static constexpr uint64_t SMEM_DESC_BASE_SW128 =
    (uint64_t(2)  << 61) | (uint64_t(1) << 46) | (uint64_t(64) << 32) | (uint64_t(1) << 16);

__device__ __forceinline__ uint64_t make_desc(uint32_t addr) {
    return SMEM_DESC_BASE_SW128 | ((uint64_t)(addr >> 4) & 0x3FFF);
}

#if HAVE_TCGEN05
__device__ __forceinline__ void tc_alloc(uint32_t smem_dst, uint32_t ncols) {
    asm volatile("tcgen05.alloc.cta_group::1.sync.aligned.shared::cta.b32 [%0], %1;"
                 :: "r"(smem_dst), "r"(ncols) : "memory");
}
__device__ __forceinline__ void tc_relinquish() {
    asm volatile("tcgen05.relinquish_alloc_permit.cta_group::1.sync.aligned;");
}
__device__ __forceinline__ void tc_dealloc(uint32_t tmem, uint32_t ncols) {
    asm volatile("tcgen05.dealloc.cta_group::1.sync.aligned.b32 %0, %1;"
                 :: "r"(tmem), "r"(ncols));
}
__device__ __forceinline__ void mbar_init(uint32_t mbar, uint32_t cnt) {
    asm volatile("mbarrier.init.shared.b64 [%0], %1;" :: "r"(mbar), "r"(cnt) : "memory");
}
__device__ __forceinline__ void mbar_inval(uint32_t mbar) {
    asm volatile("mbarrier.inval.shared.b64 [%0];" :: "r"(mbar) : "memory");
}
__device__ __forceinline__ void mbar_wait(uint32_t mbar, uint32_t parity) {
    asm volatile(
        "{\n\t.reg .pred P;\n"
        "W_%=:\n\t"
        "mbarrier.try_wait.parity.acquire.cta.shared::cta.b64 P, [%0], %1, 0x989680;\n\t"
        "@P bra.uni D_%=;\n\t"
        "bra.uni W_%=;\n"
        "D_%=:\n\t}"
        :: "r"(mbar), "r"(parity) : "memory");
}
__device__ __forceinline__ void tc_commit(uint32_t mbar) {
    asm volatile("tcgen05.commit.cta_group::1.mbarrier::arrive::one.shared::cluster.b64 [%0];"
                 :: "r"(mbar) : "memory");
}
__device__ __forceinline__ void tc_mma_bf16_ss(uint32_t d, uint64_t ad, uint64_t bd,
                                               uint32_t idesc, uint32_t en) {
    asm volatile(
        "{\n\t.reg .pred p;\n\t"
        "setp.ne.u32 p, %5, 0;\n\t"
        "tcgen05.mma.cta_group::1.kind::f16 [%0], %1, %2, %3, {%4, %4, %4, %4}, p;\n\t}"
        :: "r"(d), "l"(ad), "l"(bd), "r"(idesc), "r"(0u), "r"(en)
        : "memory");
}
#define TC_LD_32X32B_X32(r, addr) \
    asm volatile( \
        "tcgen05.ld.sync.aligned.32x32b.x32.b32 " \
        "{%0, %1, %2, %3, %4, %5, %6, %7, " \
        " %8, %9, %10, %11, %12, %13, %14, %15, " \
        " %16, %17, %18, %19, %20, %21, %22, %23, " \
        " %24, %25, %26, %27, %28, %29, %30, %31}, [%32];" \
        : "=r"((r)[0]),  "=r"((r)[1]),  "=r"((r)[2]),  "=r"((r)[3]), \
          "=r"((r)[4]),  "=r"((r)[5]),  "=r"((r)[6]),  "=r"((r)[7]), \
          "=r"((r)[8]),  "=r"((r)[9]),  "=r"((r)[10]), "=r"((r)[11]), \
          "=r"((r)[12]), "=r"((r)[13]), "=r"((r)[14]), "=r"((r)[15]), \
          "=r"((r)[16]), "=r"((r)[17]), "=r"((r)[18]), "=r"((r)[19]), \
          "=r"((r)[20]), "=r"((r)[21]), "=r"((r)[22]), "=r"((r)[23]), \
          "=r"((r)[24]), "=r"((r)[25]), "=r"((r)[26]), "=r"((r)[27]), \
          "=r"((r)[28]), "=r"((r)[29]), "=r"((r)[30]), "=r"((r)[31]) \
        : "r"(addr))
#endif  // HAVE_TCGEN05

__device__ __forceinline__ uint32_t pack2(__nv_bfloat16 a, __nv_bfloat16 b) {
    __nv_bfloat162 t; t.x = a; t.y = b;
    uint32_t u; memcpy(&u, &t, 4); return u;
}

// ---------------- weight conversion: W[K][N] fp32 -> Wt_hi/lo [N][K] bf16 --
__global__ __launch_bounds__(256)
void conv_w_kernel(const float* __restrict__ src, __nv_bfloat16* __restrict__ hi,
                   __nv_bfloat16* __restrict__ lo, int K, int N)
{
    int idx = blockIdx.x * 256 + threadIdx.x;
    if (idx >= K * N) return;
    int k = idx / N, n = idx - k * N;
    float v = src[idx];
    __nv_bfloat16 h = __float2bfloat16(v);
    float l = v - __bfloat162float(h);
    hi[(size_t)n * K + k] = h;
    lo[(size_t)n * K + k] = __float2bfloat16(l);
}

// all 6 GAT weight matrices (256x256) in one launch
__global__ __launch_bounds__(256)
void conv_w6_kernel(const float* __restrict__ src, __nv_bfloat16* __restrict__ dst)
{
    int idx = blockIdx.x * 256 + threadIdx.x;        // 6*65536 total
    int li  = idx >> 16;
    int rem = idx & 65535;
    int k = rem >> 8, n = rem & 255;
    float v = src[(size_t)li * 65536 + rem];
    __nv_bfloat16 h = __float2bfloat16(v);
    float l = v - __bfloat162float(h);
    __nv_bfloat16* base = dst + (size_t)li * 131072;
    base[n * 256 + k]         = h;
    base[65536 + n * 256 + k] = __float2bfloat16(l);
}

// ---------------- GEMM (pipelined tcgen05 + FFMA fallback) ------------------
// C_p = act(A_p[M,K] @ W_p[K,N] + bias); W split-bf16 transposed [N][K].
// Multi-path decomposition: p from blockIdx.x/pxTiles or blockIdx.y/pyTiles.
// act: 0 none, 1 tanh, 2 relu, 3 GAT (no bias; emit per-head ssrc/sdst).
__global__ __launch_bounds__(256)
void gemm_tc(const float* __restrict__ A, const __nv_bfloat16* __restrict__ Bhi,
             const __nv_bfloat16* __restrict__ Blo, const float* __restrict__ bias,
             float* __restrict__ C, int M, int K, int N, int act,
             const float* __restrict__ asrc, const float* __restrict__ adst,
             float* __restrict__ ssrc, float* __restrict__ sdst,
             int pxTiles, int pyTiles,
             long aStride, long wStride, long cStride, long sStride, int asStride)
{
    extern __shared__ char smem[];
    const int tid  = threadIdx.x;
    const int wid  = tid >> 5;
    const int lane = tid & 31;

    int bx = blockIdx.x, by = blockIdx.y, p = 0;
    if (pxTiles)      { p = bx / pxTiles; bx -= p * pxTiles; }
    else if (pyTiles) { p = by / pyTiles; by -= p * pyTiles; }
    A   += (size_t)p * aStride;
    Bhi += (size_t)p * wStride;
    Blo += (size_t)p * wStride;
    C   += (size_t)p * cStride;
    if (act == 3) {
        ssrc += (size_t)p * sStride;
        sdst += (size_t)p * sStride;
        asrc += (size_t)p * asStride;
        adst += (size_t)p * asStride;
    }
    const int m0 = by * 128;
    const int c0 = bx * 128;

#if HAVE_TCGEN05
    // =================== tcgen05 split-bf16, 2-stage pipelined =============
    const uint32_t sb = smem_u32(smem);
    // stage s at 1024 + s*65536 : AHI+0, ALO+16384, BHI+32768, BLO+49152
    if (wid == 0) { tc_alloc(sb, 128u); tc_relinquish(); }
    if (tid == 0) { mbar_init(sb + 8, 1); mbar_init(sb + 16, 1); }
    __syncthreads();
    uint32_t tmem;
    asm volatile("ld.shared.b32 %0, [%1];" : "=r"(tmem) : "r"(sb));

    const uint32_t idesc = 0x490u | (16u << 17) | (8u << 24);  // bf16, M128, N128
    const int nchunks = K >> 6;

    for (int ch = 0; ch < nchunks; ch++) {
        const int st   = ch & 1;
        const int base = 1024 + st * 65536;
        if (ch >= 2)
            mbar_wait(sb + 8 + st * 8, (uint32_t)(((ch - 2) >> 1) & 1));

        const int k0 = ch << 6;
        // A tile: fp32 -> bf16 hi/lo, SW128 [128 rows x 64 k]
        {
            const int r  = tid >> 1;
            const int cb = (tid & 1) * 32;
            const int gr = m0 + r;
            const bool vr = gr < M;
            const float* ap = A + (size_t)gr * K + k0 + cb;
#pragma unroll
            for (int j = 0; j < 8; j++) {
                float4 v = vr ? *(const float4*)(ap + j * 4)
                              : make_float4(0.f, 0.f, 0.f, 0.f);
                __nv_bfloat16 hx = __float2bfloat16(v.x);
                __nv_bfloat16 hy = __float2bfloat16(v.y);
                __nv_bfloat16 hz = __float2bfloat16(v.z);
                __nv_bfloat16 hw = __float2bfloat16(v.w);
                __nv_bfloat16 lx = __float2bfloat16(v.x - __bfloat162float(hx));
                __nv_bfloat16 ly = __float2bfloat16(v.y - __bfloat162float(hy));
                __nv_bfloat16 lz = __float2bfloat16(v.z - __bfloat162float(hz));
                __nv_bfloat16 lw = __float2bfloat16(v.w - __bfloat162float(hw));
                uint32_t byte = (uint32_t)(r * 128 + (cb + j * 4) * 2);
                uint32_t sw   = byte ^ ((byte >> 3) & 0x70);
                *(uint2*)(smem + base + sw)         = make_uint2(pack2(hx, hy), pack2(hz, hw));
                *(uint2*)(smem + base + 16384 + sw) = make_uint2(pack2(lx, ly), pack2(lz, lw));
            }
        }
        // B tiles: 128 n-rows x 64 k bf16, SW128, from [N][K] gmem
        {
#pragma unroll
            for (int it = 0; it < 4; it++) {
                int idx = it * 256 + tid;
                int n  = idx >> 3;
                int kp = idx & 7;
                uint32_t byte = (uint32_t)(n * 128 + kp * 16);
                uint32_t sw   = byte ^ ((byte >> 3) & 0x70);
                const size_t go = (size_t)(c0 + n) * K + k0 + kp * 8;
                *(uint4*)(smem + base + 32768 + sw) = *(const uint4*)(Bhi + go);
                *(uint4*)(smem + base + 49152 + sw) = *(const uint4*)(Blo + go);
            }
        }
        __syncthreads();

        if (wid == 0) {
            asm volatile("fence.proxy.async.shared::cta;" ::: "memory");
            if (elect_one_pred()) {
                uint64_t ah = make_desc(sb + base);
                uint64_t al = make_desc(sb + base + 16384);
                uint64_t bh = make_desc(sb + base + 32768);
                uint64_t bl = make_desc(sb + base + 49152);
#pragma unroll
                for (int ks = 0; ks < 4; ks++)
                    tc_mma_bf16_ss(tmem, ah + 2 * ks, bh + 2 * ks, idesc,
                                   (ch == 0 && ks == 0) ? 0u : 1u);
#pragma unroll
                for (int ks = 0; ks < 4; ks++)
                    tc_mma_bf16_ss(tmem, ah + 2 * ks, bl + 2 * ks, idesc, 1u);
#pragma unroll
                for (int ks = 0; ks < 4; ks++)
                    tc_mma_bf16_ss(tmem, al + 2 * ks, bh + 2 * ks, idesc, 1u);
                tc_commit(sb + 8 + st * 8);
            }
        }
        // no wait: loads of next chunk overlap this chunk's MMA
    }

    // drain both stages
    {
        const int uses0 = (nchunks + 1) >> 1;
        const int uses1 = nchunks >> 1;
        if (uses0 > 0) mbar_wait(sb + 8,  (uint32_t)((uses0 - 1) & 1));
        if (uses1 > 0) mbar_wait(sb + 16, (uint32_t)((uses1 - 1) & 1));
    }
    asm volatile("tcgen05.fence::after_thread_sync;" ::: "memory");

    if (wid < 4) {
        const int m = m0 + wid * 32 + lane;
        const bool valid = m < M;
        for (int cb = 0; cb < 4; cb++) {
            uint32_t r[32];
            TC_LD_32X32B_X32(r, tmem + cb * 32);
            asm volatile("tcgen05.wait::ld.sync.aligned;" ::: "memory");
            if (valid) {
                float* cp = C + (size_t)m * N + c0 + cb * 32;
                if (act == 3) {
                    float ss = 0.f, sd = 0.f;
#pragma unroll
                    for (int c = 0; c < 32; c += 4) {
                        float v0 = __uint_as_float(r[c + 0]);
                        float v1 = __uint_as_float(r[c + 1]);
                        float v2 = __uint_as_float(r[c + 2]);
                        float v3 = __uint_as_float(r[c + 3]);
                        int col = c0 + cb * 32 + c;
                        ss = fmaf(v0, asrc[col + 0], ss); sd = fmaf(v0, adst[col + 0], sd);
                        ss = fmaf(v1, asrc[col + 1], ss); sd = fmaf(v1, adst[col + 1], sd);
                        ss = fmaf(v2, asrc[col + 2], ss); sd = fmaf(v2, adst[col + 2], sd);
                        ss = fmaf(v3, asrc[col + 3], ss); sd = fmaf(v3, adst[col + 3], sd);
                        *(float4*)(cp + c) = make_float4(v0, v1, v2, v3);
                    }
                    int head = (c0 >> 5) + cb;
                    ssrc[m * 8 + head] = ss;
                    sdst[m * 8 + head] = sd;
                } else {
#pragma unroll
                    for (int c = 0; c < 32; c += 4) {
                        int col = c0 + cb * 32 + c;
                        float v0 = __uint_as_float(r[c + 0]) + (bias ? bias[col + 0] : 0.f);
                        float v1 = __uint_as_float(r[c + 1]) + (bias ? bias[col + 1] : 0.f);
                        float v2 = __uint_as_float(r[c + 2]) + (bias ? bias[col + 2] : 0.f);
                        float v3 = __uint_as_float(r[c + 3]) + (bias ? bias[col + 3] : 0.f);
                        if (act == 1) {
                            v0 = tanhf(v0); v1 = tanhf(v1); v2 = tanhf(v2); v3 = tanhf(v3);
                        } else if (act == 2) {
                            v0 = fmaxf(v0, 0.f); v1 = fmaxf(v1, 0.f);
                            v2 = fmaxf(v2, 0.f); v3 = fmaxf(v3, 0.f);
                        }
                        *(float4*)(cp + c) = make_float4(v0, v1, v2, v3);
                    }
                }
            }
        }
        asm volatile("tcgen05.fence::before_thread_sync;" ::: "memory");
    }

    __syncthreads();
    if (wid == 0) {
        if (elect_one_pred()) { mbar_inval(sb + 8); mbar_inval(sb + 16); }
        tc_dealloc(tmem, 128u);
    }

#else
    // =================== FFMA fallback (baseline sm_103) ===================
    float (*As)[128] = (float(*)[128])(smem);            //  8 KB
    float (*Bs)[128] = (float(*)[128])(smem + 8192);     //  8 KB
    float* sred_s = (float*)(smem + 16384);              //  2 KB [128][4]
    float* sred_d = (float*)(smem + 18432);              //  2 KB

    const int tx = tid & 15;
    const int ty = tid >> 4;

    float acc[8][8];
#pragma unroll
    for (int i = 0; i < 8; i++)
#pragma unroll
        for (int j = 0; j < 8; j++) acc[i][j] = 0.f;

    const int ar = tid >> 1;
    const int ac = (tid & 1) * 8;
    const int nl = tid >> 1;
    const int kb = (tid & 1) * 8;

    for (int k0 = 0; k0 < K; k0 += 16) {
        {
            int gr = m0 + ar;
            float4 a0, a1;
            if (gr < M) {
                const float* ap = A + (size_t)gr * K + k0 + ac;
                a0 = *(const float4*)(ap);
                a1 = *(const float4*)(ap + 4);
            } else {
                a0 = make_float4(0.f, 0.f, 0.f, 0.f);
                a1 = a0;
            }
            As[ac + 0][ar] = a0.x; As[ac + 1][ar] = a0.y;
            As[ac + 2][ar] = a0.z; As[ac + 3][ar] = a0.w;
            As[ac + 4][ar] = a1.x; As[ac + 5][ar] = a1.y;
            As[ac + 6][ar] = a1.z; As[ac + 7][ar] = a1.w;
        }
        {
            const size_t go = (size_t)(c0 + nl) * K + k0 + kb;
            uint4 vh = *(const uint4*)(Bhi + go);
            uint4 vl = *(const uint4*)(Blo + go);
            const __nv_bfloat16* hb = (const __nv_bfloat16*)&vh;
            const __nv_bfloat16* lb = (const __nv_bfloat16*)&vl;
#pragma unroll
            for (int j = 0; j < 8; j++)
                Bs[kb + j][nl] = __bfloat162float(hb[j]) + __bfloat162float(lb[j]);
        }
        __syncthreads();
#pragma unroll
        for (int kk = 0; kk < 16; kk++) {
            float a[8], b[8];
            *(float4*)(a)     = *(float4*)&As[kk][ty * 8];
            *(float4*)(a + 4) = *(float4*)&As[kk][ty * 8 + 4];
            *(float4*)(b)     = *(float4*)&Bs[kk][tx * 8];
            *(float4*)(b + 4) = *(float4*)&Bs[kk][tx * 8 + 4];
#pragma unroll
            for (int i = 0; i < 8; i++)
#pragma unroll
                for (int j = 0; j < 8; j++) acc[i][j] = fmaf(a[i], b[j], acc[i][j]);
        }
        __syncthreads();
    }

    const int row0 = m0 + ty * 8;
    const int colg = c0 + tx * 8;

    if (act == 3) {
        for (int idx = tid; idx < 1024; idx += 256) ((float*)(smem + 16384))[idx] = 0.f;
        __syncthreads();
        const int hb = tx >> 2;   // head within block (0..3)
#pragma unroll
        for (int i = 0; i < 8; i++) {
            int r = row0 + i;
            if (r >= M) break;
            float ss = 0.f, sd = 0.f;
            float* cp = C + (size_t)r * N + colg;
#pragma unroll
            for (int j = 0; j < 8; j++) {
                float v = acc[i][j];
                ss = fmaf(v, asrc[colg + j], ss);
                sd = fmaf(v, adst[colg + j], sd);
                cp[j] = v;
            }
            atomicAdd(&sred_s[(ty * 8 + i) * 4 + hb], ss);
            atomicAdd(&sred_d[(ty * 8 + i) * 4 + hb], sd);
        }
        __syncthreads();
        for (int idx = tid; idx < 512; idx += 256) {
            int r = idx >> 2, h = idx & 3;
            int m = m0 + r;
            if (m < M) {
                int head = (c0 >> 5) + h;
                ssrc[m * 8 + head] = sred_s[idx];
                sdst[m * 8 + head] = sred_d[idx];
            }
        }
    } else {
        float bv[8];
#pragma unroll
        for (int j = 0; j < 8; j++) bv[j] = bias ? bias[colg + j] : 0.f;
#pragma unroll
        for (int i = 0; i < 8; i++) {
            int r = row0 + i;
            if (r >= M) break;
            float* cp = C + (size_t)r * N + colg;
#pragma unroll
            for (int j = 0; j < 8; j++) {
                float v = acc[i][j] + bv[j];
                if (act == 1)      v = tanhf(v);
                else if (act == 2) v = fmaxf(v, 0.f);
                cp[j] = v;
            }
        }
    }
#endif
}

// ---------------- CSR build ------------------------------------------------
__global__ __launch_bounds__(256)
void csr_count_kernel(const int* __restrict__ edges)
{
    int idx = blockIdx.x * 256 + threadIdx.x;
    if (idx >= PP * EE) return;
    int p = idx / EE, e = idx - p * EE;
    int d = edges[(size_t)p * 2 * EE + EE + e];
    atomicAdd(&g_count[p * NN + d], 1);
}

__global__ __launch_bounds__(1024)
void csr_scan_kernel()
{
    __shared__ int warp_off[32];
    __shared__ int s_carry;
    const int lane = threadIdx.x & 31;
    const int wid  = threadIdx.x >> 5;

    for (int p = 0; p < PP; p++) {
        const int* counts = g_count  + p * NN;
        int*       indptr = g_indptr + p * (NN + 1);
        int*       cursor = g_cursor + p * NN;
        if (threadIdx.x == 0) s_carry = 0;
        __syncthreads();
        for (int base = 0; base < NN; base += 1024) {
            int i = base + (int)threadIdx.x;
            int v = (i < NN) ? counts[i] : 0;
            int incl = v;
#pragma unroll
            for (int o = 1; o < 32; o <<= 1) {
                int t = __shfl_up_sync(0xFFFFFFFFu, incl, o);
                if (lane >= o) incl += t;
            }
            if (lane == 31) warp_off[wid] = incl;
            __syncthreads();
            if (wid == 0) {
                int ws = warp_off[lane];
                int wincl = ws;
#pragma unroll
                for (int o = 1; o < 32; o <<= 1) {
                    int t = __shfl_up_sync(0xFFFFFFFFu, wincl, o);
                    if (lane >= o) wincl += t;
                }
                warp_off[lane] = wincl - ws;
            }
            __syncthreads();
            int excl = incl - v + warp_off[wid] + s_carry;
            if (i < NN) { indptr[i] = excl; cursor[i] = excl; }
            __syncthreads();
            if (threadIdx.x == 1023) s_carry = excl + v;
            __syncthreads();
        }
        if (threadIdx.x == 0) indptr[NN] = s_carry;
        __syncthreads();
    }
}

__global__ __launch_bounds__(256)
void csr_scatter_kernel(const int* __restrict__ edges)
{
    int idx = blockIdx.x * 256 + threadIdx.x;
    if (idx >= PP * EE) return;
    int p = idx / EE, e = idx - p * EE;
    int s = edges[(size_t)p * 2 * EE + e];
    int d = edges[(size_t)p * 2 * EE + EE + e];
    int pos = atomicAdd(&g_cursor[p * NN + d], 1);
    g_csrc[(size_t)p * EE + pos] = s;
}

__device__ __forceinline__ float leaky02(float v) { return (v > 0.f) ? v : 0.2f * v; }

// ---------------- fused CSR aggregate over all 3 metapaths -----------------
// one warp per (path, dst); accumulators in registers, no atomics.
__global__ __launch_bounds__(256)
void gat_aggregate_all(const float* __restrict__ hpall, const float* __restrict__ ssrcall,
                       const float* __restrict__ sdstall, const float* __restrict__ biasbase,
                       float* __restrict__ outall)
{
    int gw   = (blockIdx.x * 256 + threadIdx.x) >> 5;
    int lane = threadIdx.x & 31;
    if (gw >= PP * NN) return;
    const int p = gw / NN;
    const int n = gw - p * NN;

    const int* indptr = g_indptr + p * (NN + 1);
    const int* csrc   = g_csrc   + (size_t)p * EE;
    const float* ssrc = ssrcall + (size_t)p * NP * Hh;
    const float* sdstp= sdstall + (size_t)p * NP * Hh;
    const float* hp   = hpall   + (size_t)p * NP * F;
    const float* bias = biasbase + p * 512;
    float* out        = outall  + (size_t)p * NP * F + (size_t)n * F;

    const int beg = indptr[n];
    const int end = indptr[n + 1];

    float sd = 0.f, eself = 0.f;
    if (lane < 8) {
        sd    = sdstp[n * 8 + lane];
        eself = leaky02(ssrc[n * 8 + lane] + sd);
    }
    // pass 1: per-head max
    float m = eself;
    for (int ptr = beg; ptr < end; ptr++) {
        int s = csrc[ptr];
        if (lane < 8)
            m = fmaxf(m, leaky02(ssrc[s * 8 + lane] + sd));
    }

    // pass 2: exp-weighted gather accumulate (unrolled by 2)
    float den = (lane < 8) ? __expf(eself - m) : 0.f;
    const float exself = den;
    float accv[8];
#pragma unroll
    for (int k = 0; k < 8; k++) accv[k] = 0.f;

    int ptr = beg;
    for (; ptr + 2 <= end; ptr += 2) {
        int s0 = csrc[ptr], s1 = csrc[ptr + 1];
        float ex0 = 0.f, ex1 = 0.f;
        if (lane < 8) {
            ex0 = __expf(leaky02(ssrc[s0 * 8 + lane] + sd) - m);
            ex1 = __expf(leaky02(ssrc[s1 * 8 + lane] + sd) - m);
            den += ex0 + ex1;
        }
        float e0h[8], e1h[8];
#pragma unroll
        for (int k = 0; k < 8; k++) {
            e0h[k] = __shfl_sync(0xFFFFFFFFu, ex0, k);
            e1h[k] = __shfl_sync(0xFFFFFFFFu, ex1, k);
        }
        const float* h0p = hp + (size_t)s0 * F;
        const float* h1p = hp + (size_t)s1 * F;
#pragma unroll
        for (int k = 0; k < 8; k++)
            accv[k] = fmaf(e0h[k], h0p[k * 32 + lane], accv[k]);
#pragma unroll
        for (int k = 0; k < 8; k++)
            accv[k] = fmaf(e1h[k], h1p[k * 32 + lane], accv[k]);
    }
    if (ptr < end) {
        int s = csrc[ptr];
        float ex = 0.f;
        if (lane < 8) {
            ex = __expf(leaky02(ssrc[s * 8 + lane] + sd) - m);
            den += ex;
        }
        float exh[8];
#pragma unroll
        for (int k = 0; k < 8; k++) exh[k] = __shfl_sync(0xFFFFFFFFu, ex, k);
        const float* hsp = hp + (size_t)s * F;
#pragma unroll
        for (int k = 0; k < 8; k++)
            accv[k] = fmaf(exh[k], hsp[k * 32 + lane], accv[k]);
    }

    float exsh[8], dh[8];
#pragma unroll
    for (int k = 0; k < 8; k++) {
        exsh[k] = __shfl_sync(0xFFFFFFFFu, exself, k);
        dh[k]   = __shfl_sync(0xFFFFFFFFu, den, k);
    }
    const float* hpn = hp + (size_t)n * F;
#pragma unroll
    for (int k = 0; k < 8; k++) {
        int idx = k * 32 + lane;
        float v = (accv[k] + exsh[k] * hpn[idx]) / dh[k] + bias[idx];
        v = (v > 0.f) ? v : expm1f(v);   // ELU(alpha=1)
        out[idx] = v;
    }
}

// ---------------- semantic score (batched over all paths) ------------------
__global__ __launch_bounds__(256)
void sem_score_kernel(const float* __restrict__ W2)
{
    int gw   = (blockIdx.x * 256 + threadIdx.x) >> 5;
    int lane = threadIdx.x & 31;
    if (gw >= PP * NP) return;
    int p = gw / NP;
    int n = gw - p * NP;
    if (n >= NN) return;
    float ssum = 0.f;
#pragma unroll
    for (int k = 0; k < 4; k++) {
        int idx = k * 32 + lane;
        ssum = fmaf(g_t1[(size_t)gw * F1 + idx], W2[idx], ssum);
    }
#pragma unroll
    for (int o = 16; o > 0; o >>= 1) ssum += __shfl_xor_sync(0xFFFFFFFFu, ssum, o);
    if (lane == 0) g_sc[n * PP + p] = ssum;
}

// ---------------- semantic softmax + weighted combine ----------------------
__global__ __launch_bounds__(256)
void sem_combine_kernel()
{
    int n    = (blockIdx.x * 256 + threadIdx.x) >> 5;
    int lane = threadIdx.x & 31;
    if (n >= NN) return;
    float s0 = g_sc[n * PP + 0], s1 = g_sc[n * PP + 1], s2 = g_sc[n * PP + 2];
    float mx = fmaxf(s0, fmaxf(s1, s2));
    float w0 = __expf(s0 - mx), w1 = __expf(s1 - mx), w2 = __expf(s2 - mx);
    float inv = 1.f / (w0 + w1 + w2);
    w0 *= inv; w1 *= inv; w2 *= inv;
    const float* e0 = g_emb + (size_t)n * F;
    const float* e1 = g_emb + ((size_t)NP + n) * F;
    const float* e2 = g_emb + ((size_t)2 * NP + n) * F;
    float* zp = g_z + (size_t)n * F;
#pragma unroll
    for (int k = 0; k < 8; k++) {
        int idx = k * 32 + lane;
        zp[idx] = w0 * e0[idx] + w1 * e1[idx] + w2 * e2[idx];
    }
}

// ---------------- classifier head: logits = t2 @ W2 + b2 -------------------
__global__ __launch_bounds__(256)
void cls_out_kernel(const float* __restrict__ W2, const float* __restrict__ b2,
                    float* __restrict__ out)
{
    int n    = (blockIdx.x * 256 + threadIdx.x) >> 5;
    int lane = threadIdx.x & 31;
    if (n >= NN) return;
    float c0 = 0.f, c1 = 0.f;
#pragma unroll
    for (int k = 0; k < 4; k++) {
        int idx = k * 32 + lane;
        float t = g_t2[n * F1 + idx];
        c0 = fmaf(t, W2[idx * 2 + 0], c0);
        c1 = fmaf(t, W2[idx * 2 + 1], c1);
    }
#pragma unroll
    for (int o = 16; o > 0; o >>= 1) {
        c0 += __shfl_xor_sync(0xFFFFFFFFu, c0, o);
        c1 += __shfl_xor_sync(0xFFFFFFFFu, c1, o);
    }
    if (lane == 0) {
        out[n * 2 + 0] = c0 + b2[0];
        out[n * 2 + 1] = c1 + b2[1];
    }
}

// ---------------- driver ---------------------------------------------------
extern "C" void kernel_launch(void* const* d_in, const int* in_sizes, int n_in,
                              void* d_out, int out_size)
{
    const float* x        = (const float*)d_in[0];
    const int*   edges    = (const int*)  d_in[1];
    const float* proj_W   = (const float*)d_in[2];
    const float* proj_b   = (const float*)d_in[3];
    const float* gat_W    = (const float*)d_in[4];
    const float* gat_asrc = (const float*)d_in[5];
    const float* gat_adst = (const float*)d_in[6];
    const float* gat_b    = (const float*)d_in[7];
    const float* sem_W1   = (const float*)d_in[8];
    const float* sem_b1   = (const float*)d_in[9];
    const float* sem_W2   = (const float*)d_in[10];
    const float* cls_W1   = (const float*)d_in[11];
    const float* cls_b1   = (const float*)d_in[12];
    const float* cls_W2   = (const float*)d_in[13];
    const float* cls_b2   = (const float*)d_in[14];
    float* out = (float*)d_out;

    float *h0, *hall, *hp, *emb, *t1, *t2, *z, *ssrc, *sdst;
    int *countp;
    __nv_bfloat16* wt;
    cudaGetSymbolAddress((void**)&h0,   g_h0);
    cudaGetSymbolAddress((void**)&hall, g_hall);
    cudaGetSymbolAddress((void**)&hp,   g_hp);
    cudaGetSymbolAddress((void**)&emb,  g_emb);
    cudaGetSymbolAddress((void**)&t1,   g_t1);
    cudaGetSymbolAddress((void**)&t2,   g_t2);
    cudaGetSymbolAddress((void**)&z,    g_z);
    cudaGetSymbolAddress((void**)&ssrc, g_ssrc);
    cudaGetSymbolAddress((void**)&sdst, g_sdst);
    cudaGetSymbolAddress((void**)&countp, g_count);
    cudaGetSymbolAddress((void**)&wt,     g_wt);

    const int SMEM = 1024 + 2 * 65536;   // 132096 (tcgen05 2-stage)
    cudaFuncSetAttribute(gemm_tc, cudaFuncAttributeMaxDynamicSharedMemorySize, SMEM);

    const int MT = NP / 128;                         // 391
    const int nodeWarpBlocks  = (NN + 7) / 8;
    const int allNodeWarpBlks = (PP * NN + 7) / 8;
    const int semWarpBlks     = (PP * NP + 7) / 8;
    const int allEdgeBlocks   = (PP * EE + 255) / 256;

    const long NPF = (long)NP * F;
    const long NP8 = (long)NP * Hh;

    // --- weight split/transposition ----------------------------------------
    conv_w_kernel<<<(128 * 256 + 255) / 256, 256>>>(proj_W, wt, wt + 32768, 128, 256);
    conv_w6_kernel<<<(6 * 65536 + 255) / 256, 256>>>(gat_W, wt + 65536);
    conv_w_kernel<<<(256 * 128 + 255) / 256, 256>>>(sem_W1, wt + 851968, wt + 884736, 256, 128);
    conv_w_kernel<<<(256 * 128 + 255) / 256, 256>>>(cls_W1, wt + 917504, wt + 950272, 256, 128);

    // --- CSR build ----------------------------------------------------------
    cudaMemsetAsync(countp, 0, sizeof(int) * PP * NN);
    csr_count_kernel<<<allEdgeBlocks, 256>>>(edges);
    csr_scan_kernel<<<1, 1024>>>();
    csr_scatter_kernel<<<allEdgeBlocks, 256>>>(edges);

    // h0 = x @ proj_W + proj_b   (M=NN guard; pad rows of h0 stay 0)
    gemm_tc<<<dim3(2, MT), 256, SMEM>>>(x, wt, wt + 32768, proj_b, h0,
                                        NN, 128, 256, 0,
                                        nullptr, nullptr, nullptr, nullptr,
                                        0, 0, 0, 0, 0, 0, 0);

    // --- layer 1 (all 3 metapaths in one launch each) -----------------------
    gemm_tc<<<dim3(6, MT), 256, SMEM>>>(h0, wt + 65536, wt + 131072, nullptr, hp,
                                        NP, 256, 256, 3,
                                        gat_asrc, gat_adst, ssrc, sdst,
                                        2, 0, 0, 262144, NPF, NP8, 512);
    gat_aggregate_all<<<allNodeWarpBlks, 256>>>(hp, ssrc, sdst, gat_b, hall);

    // --- layer 2 ------------------------------------------------------------
    gemm_tc<<<dim3(2, 3 * MT), 256, SMEM>>>(hall, wt + 65536 + 131072, wt + 65536 + 196608,
                                            nullptr, hp,
                                            NP, 256, 256, 3,
                                            gat_asrc + 256, gat_adst + 256, ssrc, sdst,
                                            0, MT, NPF, 262144, NPF, NP8, 512);
    gat_aggregate_all<<<allNodeWarpBlks, 256>>>(hp, ssrc, sdst, gat_b + 256, emb);

    // --- semantic attention (batched M = 3*NP) ------------------------------
    gemm_tc<<<dim3(1, 3 * MT), 256, SMEM>>>(emb, wt + 851968, wt + 884736, sem_b1, t1,
                                            3 * NP, 256, 128, 1,
                                            nullptr, nullptr, nullptr, nullptr,
                                            0, 0, 0, 0, 0, 0, 0);
    sem_score_kernel<<<semWarpBlks, 256>>>(sem_W2);
    sem_combine_kernel<<<nodeWarpBlocks, 256>>>();

    // --- classifier ---------------------------------------------------------
    gemm_tc<<<dim3(1, MT), 256, SMEM>>>(z, wt + 917504, wt + 950272, cls_b1, t2,
                                        NN, 256, 128, 2,
                                        nullptr, nullptr, nullptr, nullptr,
                                        0, 0, 0, 0, 0, 0, 0);
    cls_out_kernel<<<nodeWarpBlocks, 256>>>(cls_W2, cls_b2, out);
}

// round 14
// speedup vs baseline: 1.0156x; 1.0156x over previous
#include <cuda_runtime.h>
#include <cuda_bf16.h>
#include <math.h>
#include <stdint.h>
#include <string.h>

// Problem constants (fixed by the dataset)
constexpr int NN  = 50000;   // nodes
constexpr int NP  = 50048;   // nodes padded to 128 (391 tiles)
constexpr int F   = 256;     // hidden
constexpr int Hh  = 8;       // heads
constexpr int EE  = 800000;  // edges per metapath
constexpr int PP  = 3;       // metapaths
constexpr int F1  = 128;     // MLP hidden

// ---------------- scratch (device globals; zero-initialized) ---------------
__device__ __align__(16) float g_h0 [NP * F];           // pad rows stay 0
__device__ __align__(16) float g_hall[PP * NP * F];     // layer-1 outputs (stacked)
__device__ __align__(16) float g_hp  [PP * NP * F];     // GEMM outputs (stacked)
__device__ __align__(16) float g_ssrc[PP * NP * Hh];
__device__ __align__(16) float g_sdst[PP * NP * Hh];
__device__ __align__(16) float g_emb [PP * NP * F];
__device__ __align__(16) float g_t1  [PP * NP * F1];
__device__ __align__(16) float g_sc  [NN * PP];
__device__ __align__(16) float g_z   [NN * F];
__device__ __align__(16) float g_t2  [NN * F1];

// CSR structures
__device__ int g_count [PP * NN];
__device__ int g_indptr[PP * (NN + 1)];
__device__ int g_cursor[PP * NN];
__device__ int g_csrc  [PP * EE];

// split-bf16 weights, transposed to [N][K], hi then lo per matrix
__device__ __align__(16) __nv_bfloat16 g_wt[983040];

// feature gate: tcgen05 only exists in an arch-specific (sm_103a/100a) pass
#if defined(__CUDA_ARCH_FEAT_SM103_ALL) || defined(__CUDA_ARCH_FEAT_SM100_ALL) || defined(__CUDA_ARCH_FEAT_SM101_ALL)
#define HAVE_TCGEN05 1
#else
#define HAVE_TCGEN05 0
#endif

// ---------------- PTX helpers ----------------------------------------------
__device__ __forceinline__ uint32_t elect_one_pred() {
    uint32_t pred;
    asm volatile(
        "{\n\t.reg .pred p;\n\t"
        "elect.sync _|p, 0xFFFFFFFF;\n\t"
        "selp.b32 %0, 1, 0, p;\n\t}"
        : "=r"(pred));
    return pred;
}
__device__ __forceinline__ uint32_t smem_u32(const void* p) {
    uint32_t a;
    asm("{ .reg .u64 t; cvta.to.shared.u64 t, %1; cvt.u32.u64 %0, t; }"
        : "=r"(a) : "l"(p));
    return a;
}

static constexpr uint64_t SMEM_DESC_BASE_SW128 =
    (uint64_t(2)  << 61) | (uint64_t(1) << 46) | (uint64_t(64) << 32) | (uint64_t(1) << 16);

__device__ __forceinline__ uint64_t make_desc(uint32_t addr) {
    return SMEM_DESC_BASE_SW128 | ((uint64_t)(addr >> 4) & 0x3FFF);
}

#if HAVE_TCGEN05
__device__ __forceinline__ void tc_alloc(uint32_t smem_dst, uint32_t ncols) {
    asm volatile("tcgen05.alloc.cta_group::1.sync.aligned.shared::cta.b32 [%0], %1;"
                 :: "r"(smem_dst), "r"(ncols) : "memory");
}
__device__ __forceinline__ void tc_relinquish() {
    asm volatile("tcgen05.relinquish_alloc_permit.cta_group::1.sync.aligned;");
}
__device__ __forceinline__ void tc_dealloc(uint32_t tmem, uint32_t ncols) {
    asm volatile("tcgen05.dealloc.cta_group::1.sync.aligned.b32 %0, %1;"
                 :: "r"(tmem), "r"(ncols));
}
__device__ __forceinline__ void mbar_init(uint32_t mbar, uint32_t cnt) {
    asm volatile("mbarrier.init.shared.b64 [%0], %1;" :: "r"(mbar), "r"(cnt) : "memory");
}
__device__ __forceinline__ void mbar_inval(uint32_t mbar) {
    asm volatile("mbarrier.inval.shared.b64 [%0];" :: "r"(mbar) : "memory");
}
__device__ __forceinline__ void mbar_wait(uint32_t mbar, uint32_t parity) {
    asm volatile(
        "{\n\t.reg .pred P;\n"
        "W_%=:\n\t"
        "mbarrier.try_wait.parity.acquire.cta.shared::cta.b64 P, [%0], %1, 0x989680;\n\t"
        "@P bra.uni D_%=;\n\t"
        "bra.uni W_%=;\n"
        "D_%=:\n\t}"
        :: "r"(mbar), "r"(parity) : "memory");
}
__device__ __forceinline__ void tc_commit(uint32_t mbar) {
    asm volatile("tcgen05.commit.cta_group::1.mbarrier::arrive::one.shared::cluster.b64 [%0];"
                 :: "r"(mbar) : "memory");
}
__device__ __forceinline__ void tc_mma_bf16_ss(uint32_t d, uint64_t ad, uint64_t bd,
                                               uint32_t idesc, uint32_t en) {
    asm volatile(
        "{\n\t.reg .pred p;\n\t"
        "setp.ne.u32 p, %5, 0;\n\t"
        "tcgen05.mma.cta_group::1.kind::f16 [%0], %1, %2, %3, {%4, %4, %4, %4}, p;\n\t}"
        :: "r"(d), "l"(ad), "l"(bd), "r"(idesc), "r"(0u), "r"(en)
        : "memory");
}
#define TC_LD_32X32B_X32(r, addr) \
    asm volatile( \
        "tcgen05.ld.sync.aligned.32x32b.x32.b32 " \
        "{%0, %1, %2, %3, %4, %5, %6, %7, " \
        " %8, %9, %10, %11, %12, %13, %14, %15, " \
        " %16, %17, %18, %19, %20, %21, %22, %23, " \
        " %24, %25, %26, %27, %28, %29, %30, %31}, [%32];" \
        : "=r"((r)[0]),  "=r"((r)[1]),  "=r"((r)[2]),  "=r"((r)[3]), \
          "=r"((r)[4]),  "=r"((r)[5]),  "=r"((r)[6]),  "=r"((r)[7]), \
          "=r"((r)[8]),  "=r"((r)[9]),  "=r"((r)[10]), "=r"((r)[11]), \
          "=r"((r)[12]), "=r"((r)[13]), "=r"((r)[14]), "=r"((r)[15]), \
          "=r"((r)[16]), "=r"((r)[17]), "=r"((r)[18]), "=r"((r)[19]), \
          "=r"((r)[20]), "=r"((r)[21]), "=r"((r)[22]), "=r"((r)[23]), \
          "=r"((r)[24]), "=r"((r)[25]), "=r"((r)[26]), "=r"((r)[27]), \
          "=r"((r)[28]), "=r"((r)[29]), "=r"((r)[30]), "=r"((r)[31]) \
        : "r"(addr))
#endif  // HAVE_TCGEN05

__device__ __forceinline__ uint32_t pack2(__nv_bfloat16 a, __nv_bfloat16 b) {
    __nv_bfloat162 t; t.x = a; t.y = b;
    uint32_t u; memcpy(&u, &t, 4); return u;
}

// ---------------- weight conversion: W[K][N] fp32 -> Wt_hi/lo [N][K] bf16 --
__global__ __launch_bounds__(256)
void conv_w_kernel(const float* __restrict__ src, __nv_bfloat16* __restrict__ hi,
                   __nv_bfloat16* __restrict__ lo, int K, int N)
{
    int idx = blockIdx.x * 256 + threadIdx.x;
    if (idx >= K * N) return;
    int k = idx / N, n = idx - k * N;
    float v = src[idx];
    __nv_bfloat16 h = __float2bfloat16(v);
    float l = v - __bfloat162float(h);
    hi[(size_t)n * K + k] = h;
    lo[(size_t)n * K + k] = __float2bfloat16(l);
}

// all 6 GAT weight matrices (256x256) in one launch
__global__ __launch_bounds__(256)
void conv_w6_kernel(const float* __restrict__ src, __nv_bfloat16* __restrict__ dst)
{
    int idx = blockIdx.x * 256 + threadIdx.x;        // 6*65536 total
    int li  = idx >> 16;
    int rem = idx & 65535;
    int k = rem >> 8, n = rem & 255;
    float v = src[(size_t)li * 65536 + rem];
    __nv_bfloat16 h = __float2bfloat16(v);
    float l = v - __bfloat162float(h);
    __nv_bfloat16* base = dst + (size_t)li * 131072;
    base[n * 256 + k]         = h;
    base[65536 + n * 256 + k] = __float2bfloat16(l);
}

// ---------------- GEMM (single-stage tcgen05, occ-3 + FFMA fallback) --------
// C_p = act(A_p[M,K] @ W_p[K,N] + bias); W split-bf16 transposed [N][K].
// Multi-path decomposition: p from blockIdx.x/pxTiles or blockIdx.y/pyTiles.
// act: 0 none, 1 tanh, 2 relu, 3 GAT (no bias; emit per-head ssrc/sdst).
__global__ __launch_bounds__(256)
void gemm_tc(const float* __restrict__ A, const __nv_bfloat16* __restrict__ Bhi,
             const __nv_bfloat16* __restrict__ Blo, const float* __restrict__ bias,
             float* __restrict__ C, int M, int K, int N, int act,
             const float* __restrict__ asrc, const float* __restrict__ adst,
             float* __restrict__ ssrc, float* __restrict__ sdst,
             int pxTiles, int pyTiles,
             long aStride, long wStride, long cStride, long sStride, int asStride)
{
    extern __shared__ char smem[];
    const int tid  = threadIdx.x;
    const int wid  = tid >> 5;
    const int lane = tid & 31;

    int bx = blockIdx.x, by = blockIdx.y, p = 0;
    if (pxTiles)      { p = bx / pxTiles; bx -= p * pxTiles; }
    else if (pyTiles) { p = by / pyTiles; by -= p * pyTiles; }
    A   += (size_t)p * aStride;
    Bhi += (size_t)p * wStride;
    Blo += (size_t)p * wStride;
    C   += (size_t)p * cStride;
    if (act == 3) {
        ssrc += (size_t)p * sStride;
        sdst += (size_t)p * sStride;
        asrc += (size_t)p * asStride;
        adst += (size_t)p * asStride;
    }
    const int m0 = by * 128;
    const int c0 = bx * 128;

#if HAVE_TCGEN05
    // =================== tcgen05 split-bf16, single-stage (occ 3) ==========
    const uint32_t sb = smem_u32(smem);
    const int SM_AHI = 1024;
    const int SM_ALO = 1024 + 16384;
    const int SM_BHI = 1024 + 32768;
    const int SM_BLO = 1024 + 49152;

    if (wid == 0) { tc_alloc(sb, 128u); tc_relinquish(); }
    if (tid == 0) { mbar_init(sb + 8, 1); }
    __syncthreads();
    uint32_t tmem;
    asm volatile("ld.shared.b32 %0, [%1];" : "=r"(tmem) : "r"(sb));

    const uint32_t idesc = 0x490u | (16u << 17) | (8u << 24);  // bf16, M128, N128
    const int nchunks = K >> 6;

    for (int ch = 0; ch < nchunks; ch++) {
        const int k0 = ch << 6;
        // A tile: fp32 -> bf16 hi/lo, SW128 [128 rows x 64 k]
        {
            const int r  = tid >> 1;
            const int cb = (tid & 1) * 32;
            const int gr = m0 + r;
            const bool vr = gr < M;
            const float* ap = A + (size_t)gr * K + k0 + cb;
#pragma unroll
            for (int j = 0; j < 8; j++) {
                float4 v = vr ? *(const float4*)(ap + j * 4)
                              : make_float4(0.f, 0.f, 0.f, 0.f);
                __nv_bfloat16 hx = __float2bfloat16(v.x);
                __nv_bfloat16 hy = __float2bfloat16(v.y);
                __nv_bfloat16 hz = __float2bfloat16(v.z);
                __nv_bfloat16 hw = __float2bfloat16(v.w);
                __nv_bfloat16 lx = __float2bfloat16(v.x - __bfloat162float(hx));
                __nv_bfloat16 ly = __float2bfloat16(v.y - __bfloat162float(hy));
                __nv_bfloat16 lz = __float2bfloat16(v.z - __bfloat162float(hz));
                __nv_bfloat16 lw = __float2bfloat16(v.w - __bfloat162float(hw));
                uint32_t byte = (uint32_t)(r * 128 + (cb + j * 4) * 2);
                uint32_t sw   = byte ^ ((byte >> 3) & 0x70);
                *(uint2*)(smem + SM_AHI + sw) = make_uint2(pack2(hx, hy), pack2(hz, hw));
                *(uint2*)(smem + SM_ALO + sw) = make_uint2(pack2(lx, ly), pack2(lz, lw));
            }
        }
        // B tiles: 128 n-rows x 64 k bf16, SW128, from [N][K] gmem
        {
#pragma unroll
            for (int it = 0; it < 4; it++) {
                int idx = it * 256 + tid;
                int n  = idx >> 3;
                int kp = idx & 7;
                uint32_t byte = (uint32_t)(n * 128 + kp * 16);
                uint32_t sw   = byte ^ ((byte >> 3) & 0x70);
                const size_t go = (size_t)(c0 + n) * K + k0 + kp * 8;
                *(uint4*)(smem + SM_BHI + sw) = *(const uint4*)(Bhi + go);
                *(uint4*)(smem + SM_BLO + sw) = *(const uint4*)(Blo + go);
            }
        }
        __syncthreads();

        if (wid == 0) {
            asm volatile("fence.proxy.async.shared::cta;" ::: "memory");
            if (elect_one_pred()) {
                uint64_t ah = make_desc(sb + SM_AHI);
                uint64_t al = make_desc(sb + SM_ALO);
                uint64_t bh = make_desc(sb + SM_BHI);
                uint64_t bl = make_desc(sb + SM_BLO);
#pragma unroll
                for (int ks = 0; ks < 4; ks++)
                    tc_mma_bf16_ss(tmem, ah + 2 * ks, bh + 2 * ks, idesc,
                                   (ch == 0 && ks == 0) ? 0u : 1u);
#pragma unroll
                for (int ks = 0; ks < 4; ks++)
                    tc_mma_bf16_ss(tmem, ah + 2 * ks, bl + 2 * ks, idesc, 1u);
#pragma unroll
                for (int ks = 0; ks < 4; ks++)
                    tc_mma_bf16_ss(tmem, al + 2 * ks, bh + 2 * ks, idesc, 1u);
                tc_commit(sb + 8);
            }
        }
        mbar_wait(sb + 8, (uint32_t)(ch & 1));
    }

    asm volatile("tcgen05.fence::after_thread_sync;" ::: "memory");

    if (wid < 4) {
        const int m = m0 + wid * 32 + lane;
        const bool valid = m < M;
        for (int cb = 0; cb < 4; cb++) {
            uint32_t r[32];
            TC_LD_32X32B_X32(r, tmem + cb * 32);
            asm volatile("tcgen05.wait::ld.sync.aligned;" ::: "memory");
            if (valid) {
                float* cp = C + (size_t)m * N + c0 + cb * 32;
                if (act == 3) {
                    float ss = 0.f, sd = 0.f;
#pragma unroll
                    for (int c = 0; c < 32; c += 4) {
                        float v0 = __uint_as_float(r[c + 0]);
                        float v1 = __uint_as_float(r[c + 1]);
                        float v2 = __uint_as_float(r[c + 2]);
                        float v3 = __uint_as_float(r[c + 3]);
                        int col = c0 + cb * 32 + c;
                        ss = fmaf(v0, asrc[col + 0], ss); sd = fmaf(v0, adst[col + 0], sd);
                        ss = fmaf(v1, asrc[col + 1], ss); sd = fmaf(v1, adst[col + 1], sd);
                        ss = fmaf(v2, asrc[col + 2], ss); sd = fmaf(v2, adst[col + 2], sd);
                        ss = fmaf(v3, asrc[col + 3], ss); sd = fmaf(v3, adst[col + 3], sd);
                        *(float4*)(cp + c) = make_float4(v0, v1, v2, v3);
                    }
                    int head = (c0 >> 5) + cb;
                    ssrc[m * 8 + head] = ss;
                    sdst[m * 8 + head] = sd;
                } else {
#pragma unroll
                    for (int c = 0; c < 32; c += 4) {
                        int col = c0 + cb * 32 + c;
                        float v0 = __uint_as_float(r[c + 0]) + (bias ? bias[col + 0] : 0.f);
                        float v1 = __uint_as_float(r[c + 1]) + (bias ? bias[col + 1] : 0.f);
                        float v2 = __uint_as_float(r[c + 2]) + (bias ? bias[col + 2] : 0.f);
                        float v3 = __uint_as_float(r[c + 3]) + (bias ? bias[col + 3] : 0.f);
                        if (act == 1) {
                            v0 = tanhf(v0); v1 = tanhf(v1); v2 = tanhf(v2); v3 = tanhf(v3);
                        } else if (act == 2) {
                            v0 = fmaxf(v0, 0.f); v1 = fmaxf(v1, 0.f);
                            v2 = fmaxf(v2, 0.f); v3 = fmaxf(v3, 0.f);
                        }
                        *(float4*)(cp + c) = make_float4(v0, v1, v2, v3);
                    }
                }
            }
        }
        asm volatile("tcgen05.fence::before_thread_sync;" ::: "memory");
    }

    __syncthreads();
    if (wid == 0) {
        if (elect_one_pred()) mbar_inval(sb + 8);
        tc_dealloc(tmem, 128u);
    }

#else
    // =================== FFMA fallback (baseline sm_103) ===================
    float (*As)[128] = (float(*)[128])(smem);            //  8 KB
    float (*Bs)[128] = (float(*)[128])(smem + 8192);     //  8 KB
    float* sred_s = (float*)(smem + 16384);              //  2 KB [128][4]
    float* sred_d = (float*)(smem + 18432);              //  2 KB

    const int tx = tid & 15;
    const int ty = tid >> 4;

    float acc[8][8];
#pragma unroll
    for (int i = 0; i < 8; i++)
#pragma unroll
        for (int j = 0; j < 8; j++) acc[i][j] = 0.f;

    const int ar = tid >> 1;
    const int ac = (tid & 1) * 8;
    const int nl = tid >> 1;
    const int kb = (tid & 1) * 8;

    for (int k0 = 0; k0 < K; k0 += 16) {
        {
            int gr = m0 + ar;
            float4 a0, a1;
            if (gr < M) {
                const float* ap = A + (size_t)gr * K + k0 + ac;
                a0 = *(const float4*)(ap);
                a1 = *(const float4*)(ap + 4);
            } else {
                a0 = make_float4(0.f, 0.f, 0.f, 0.f);
                a1 = a0;
            }
            As[ac + 0][ar] = a0.x; As[ac + 1][ar] = a0.y;
            As[ac + 2][ar] = a0.z; As[ac + 3][ar] = a0.w;
            As[ac + 4][ar] = a1.x; As[ac + 5][ar] = a1.y;
            As[ac + 6][ar] = a1.z; As[ac + 7][ar] = a1.w;
        }
        {
            const size_t go = (size_t)(c0 + nl) * K + k0 + kb;
            uint4 vh = *(const uint4*)(Bhi + go);
            uint4 vl = *(const uint4*)(Blo + go);
            const __nv_bfloat16* hb = (const __nv_bfloat16*)&vh;
            const __nv_bfloat16* lb = (const __nv_bfloat16*)&vl;
#pragma unroll
            for (int j = 0; j < 8; j++)
                Bs[kb + j][nl] = __bfloat162float(hb[j]) + __bfloat162float(lb[j]);
        }
        __syncthreads();
#pragma unroll
        for (int kk = 0; kk < 16; kk++) {
            float a[8], b[8];
            *(float4*)(a)     = *(float4*)&As[kk][ty * 8];
            *(float4*)(a + 4) = *(float4*)&As[kk][ty * 8 + 4];
            *(float4*)(b)     = *(float4*)&Bs[kk][tx * 8];
            *(float4*)(b + 4) = *(float4*)&Bs[kk][tx * 8 + 4];
#pragma unroll
            for (int i = 0; i < 8; i++)
#pragma unroll
                for (int j = 0; j < 8; j++) acc[i][j] = fmaf(a[i], b[j], acc[i][j]);
        }
        __syncthreads();
    }

    const int row0 = m0 + ty * 8;
    const int colg = c0 + tx * 8;

    if (act == 3) {
        for (int idx = tid; idx < 1024; idx += 256) ((float*)(smem + 16384))[idx] = 0.f;
        __syncthreads();
        const int hb = tx >> 2;   // head within block (0..3)
#pragma unroll
        for (int i = 0; i < 8; i++) {
            int r = row0 + i;
            if (r >= M) break;
            float ss = 0.f, sd = 0.f;
            float* cp = C + (size_t)r * N + colg;
#pragma unroll
            for (int j = 0; j < 8; j++) {
                float v = acc[i][j];
                ss = fmaf(v, asrc[colg + j], ss);
                sd = fmaf(v, adst[colg + j], sd);
                cp[j] = v;
            }
            atomicAdd(&sred_s[(ty * 8 + i) * 4 + hb], ss);
            atomicAdd(&sred_d[(ty * 8 + i) * 4 + hb], sd);
        }
        __syncthreads();
        for (int idx = tid; idx < 512; idx += 256) {
            int r = idx >> 2, h = idx & 3;
            int m = m0 + r;
            if (m < M) {
                int head = (c0 >> 5) + h;
                ssrc[m * 8 + head] = sred_s[idx];
                sdst[m * 8 + head] = sred_d[idx];
            }
        }
    } else {
        float bv[8];
#pragma unroll
        for (int j = 0; j < 8; j++) bv[j] = bias ? bias[colg + j] : 0.f;
#pragma unroll
        for (int i = 0; i < 8; i++) {
            int r = row0 + i;
            if (r >= M) break;
            float* cp = C + (size_t)r * N + colg;
#pragma unroll
            for (int j = 0; j < 8; j++) {
                float v = acc[i][j] + bv[j];
                if (act == 1)      v = tanhf(v);
                else if (act == 2) v = fmaxf(v, 0.f);
                cp[j] = v;
            }
        }
    }
#endif
}

// ---------------- CSR build ------------------------------------------------
__global__ __launch_bounds__(256)
void csr_count_kernel(const int* __restrict__ edges)
{
    int idx = blockIdx.x * 256 + threadIdx.x;
    if (idx >= PP * EE) return;
    int p = idx / EE, e = idx - p * EE;
    int d = edges[(size_t)p * 2 * EE + EE + e];
    atomicAdd(&g_count[p * NN + d], 1);
}

__global__ __launch_bounds__(1024)
void csr_scan_kernel()
{
    __shared__ int warp_off[32];
    __shared__ int s_carry;
    const int lane = threadIdx.x & 31;
    const int wid  = threadIdx.x >> 5;

    for (int p = 0; p < PP; p++) {
        const int* counts = g_count  + p * NN;
        int*       indptr = g_indptr + p * (NN + 1);
        int*       cursor = g_cursor + p * NN;
        if (threadIdx.x == 0) s_carry = 0;
        __syncthreads();
        for (int base = 0; base < NN; base += 1024) {
            int i = base + (int)threadIdx.x;
            int v = (i < NN) ? counts[i] : 0;
            int incl = v;
#pragma unroll
            for (int o = 1; o < 32; o <<= 1) {
                int t = __shfl_up_sync(0xFFFFFFFFu, incl, o);
                if (lane >= o) incl += t;
            }
            if (lane == 31) warp_off[wid] = incl;
            __syncthreads();
            if (wid == 0) {
                int ws = warp_off[lane];
                int wincl = ws;
#pragma unroll
                for (int o = 1; o < 32; o <<= 1) {
                    int t = __shfl_up_sync(0xFFFFFFFFu, wincl, o);
                    if (lane >= o) wincl += t;
                }
                warp_off[lane] = wincl - ws;
            }
            __syncthreads();
            int excl = incl - v + warp_off[wid] + s_carry;
            if (i < NN) { indptr[i] = excl; cursor[i] = excl; }
            __syncthreads();
            if (threadIdx.x == 1023) s_carry = excl + v;
            __syncthreads();
        }
        if (threadIdx.x == 0) indptr[NN] = s_carry;
        __syncthreads();
    }
}

__global__ __launch_bounds__(256)
void csr_scatter_kernel(const int* __restrict__ edges)
{
    int idx = blockIdx.x * 256 + threadIdx.x;
    if (idx >= PP * EE) return;
    int p = idx / EE, e = idx - p * EE;
    int s = edges[(size_t)p * 2 * EE + e];
    int d = edges[(size_t)p * 2 * EE + EE + e];
    int pos = atomicAdd(&g_cursor[p * NN + d], 1);
    g_csrc[(size_t)p * EE + pos] = s;
}

__device__ __forceinline__ float leaky02(float v) { return (v > 0.f) ? v : 0.2f * v; }

// ---------------- fused CSR aggregate over all 3 metapaths -----------------
// one warp per (path, dst); accumulators in registers, no atomics.
__global__ __launch_bounds__(256)
void gat_aggregate_all(const float* __restrict__ hpall, const float* __restrict__ ssrcall,
                       const float* __restrict__ sdstall, const float* __restrict__ biasbase,
                       float* __restrict__ outall)
{
    int gw   = (blockIdx.x * 256 + threadIdx.x) >> 5;
    int lane = threadIdx.x & 31;
    if (gw >= PP * NN) return;
    const int p = gw / NN;
    const int n = gw - p * NN;

    const int* indptr = g_indptr + p * (NN + 1);
    const int* csrc   = g_csrc   + (size_t)p * EE;
    const float* ssrc = ssrcall + (size_t)p * NP * Hh;
    const float* sdstp= sdstall + (size_t)p * NP * Hh;
    const float* hp   = hpall   + (size_t)p * NP * F;
    const float* bias = biasbase + p * 512;
    float* out        = outall  + (size_t)p * NP * F + (size_t)n * F;

    const int beg = indptr[n];
    const int end = indptr[n + 1];

    float sd = 0.f, eself = 0.f;
    if (lane < 8) {
        sd    = sdstp[n * 8 + lane];
        eself = leaky02(ssrc[n * 8 + lane] + sd);
    }
    // pass 1: per-head max
    float m = eself;
    for (int ptr = beg; ptr < end; ptr++) {
        int s = csrc[ptr];
        if (lane < 8)
            m = fmaxf(m, leaky02(ssrc[s * 8 + lane] + sd));
    }

    // pass 2: exp-weighted gather accumulate (unrolled by 2)
    float den = (lane < 8) ? __expf(eself - m) : 0.f;
    const float exself = den;
    float accv[8];
#pragma unroll
    for (int k = 0; k < 8; k++) accv[k] = 0.f;

    int ptr = beg;
    for (; ptr + 2 <= end; ptr += 2) {
        int s0 = csrc[ptr], s1 = csrc[ptr + 1];
        float ex0 = 0.f, ex1 = 0.f;
        if (lane < 8) {
            ex0 = __expf(leaky02(ssrc[s0 * 8 + lane] + sd) - m);
            ex1 = __expf(leaky02(ssrc[s1 * 8 + lane] + sd) - m);
            den += ex0 + ex1;
        }
        float e0h[8], e1h[8];
#pragma unroll
        for (int k = 0; k < 8; k++) {
            e0h[k] = __shfl_sync(0xFFFFFFFFu, ex0, k);
            e1h[k] = __shfl_sync(0xFFFFFFFFu, ex1, k);
        }
        const float* h0p = hp + (size_t)s0 * F;
        const float* h1p = hp + (size_t)s1 * F;
#pragma unroll
        for (int k = 0; k < 8; k++)
            accv[k] = fmaf(e0h[k], h0p[k * 32 + lane], accv[k]);
#pragma unroll
        for (int k = 0; k < 8; k++)
            accv[k] = fmaf(e1h[k], h1p[k * 32 + lane], accv[k]);
    }
    if (ptr < end) {
        int s = csrc[ptr];
        float ex = 0.f;
        if (lane < 8) {
            ex = __expf(leaky02(ssrc[s * 8 + lane] + sd) - m);
            den += ex;
        }
        float exh[8];
#pragma unroll
        for (int k = 0; k < 8; k++) exh[k] = __shfl_sync(0xFFFFFFFFu, ex, k);
        const float* hsp = hp + (size_t)s * F;
#pragma unroll
        for (int k = 0; k < 8; k++)
            accv[k] = fmaf(exh[k], hsp[k * 32 + lane], accv[k]);
    }

    float exsh[8], dh[8];
#pragma unroll
    for (int k = 0; k < 8; k++) {
        exsh[k] = __shfl_sync(0xFFFFFFFFu, exself, k);
        dh[k]   = __shfl_sync(0xFFFFFFFFu, den, k);
    }
    const float* hpn = hp + (size_t)n * F;
#pragma unroll
    for (int k = 0; k < 8; k++) {
        int idx = k * 32 + lane;
        float v = (accv[k] + exsh[k] * hpn[idx]) / dh[k] + bias[idx];
        v = (v > 0.f) ? v : expm1f(v);   // ELU(alpha=1)
        out[idx] = v;
    }
}

// ---------------- semantic score (batched over all paths) ------------------
__global__ __launch_bounds__(256)
void sem_score_kernel(const float* __restrict__ W2)
{
    int gw   = (blockIdx.x * 256 + threadIdx.x) >> 5;
    int lane = threadIdx.x & 31;
    if (gw >= PP * NP) return;
    int p = gw / NP;
    int n = gw - p * NP;
    if (n >= NN) return;
    float ssum = 0.f;
#pragma unroll
    for (int k = 0; k < 4; k++) {
        int idx = k * 32 + lane;
        ssum = fmaf(g_t1[(size_t)gw * F1 + idx], W2[idx], ssum);
    }
#pragma unroll
    for (int o = 16; o > 0; o >>= 1) ssum += __shfl_xor_sync(0xFFFFFFFFu, ssum, o);
    if (lane == 0) g_sc[n * PP + p] = ssum;
}

// ---------------- semantic softmax + weighted combine ----------------------
__global__ __launch_bounds__(256)
void sem_combine_kernel()
{
    int n    = (blockIdx.x * 256 + threadIdx.x) >> 5;
    int lane = threadIdx.x & 31;
    if (n >= NN) return;
    float s0 = g_sc[n * PP + 0], s1 = g_sc[n * PP + 1], s2 = g_sc[n * PP + 2];
    float mx = fmaxf(s0, fmaxf(s1, s2));
    float w0 = __expf(s0 - mx), w1 = __expf(s1 - mx), w2 = __expf(s2 - mx);
    float inv = 1.f / (w0 + w1 + w2);
    w0 *= inv; w1 *= inv; w2 *= inv;
    const float* e0 = g_emb + (size_t)n * F;
    const float* e1 = g_emb + ((size_t)NP + n) * F;
    const float* e2 = g_emb + ((size_t)2 * NP + n) * F;
    float* zp = g_z + (size_t)n * F;
#pragma unroll
    for (int k = 0; k < 8; k++) {
        int idx = k * 32 + lane;
        zp[idx] = w0 * e0[idx] + w1 * e1[idx] + w2 * e2[idx];
    }
}

// ---------------- classifier head: logits = t2 @ W2 + b2 -------------------
__global__ __launch_bounds__(256)
void cls_out_kernel(const float* __restrict__ W2, const float* __restrict__ b2,
                    float* __restrict__ out)
{
    int n    = (blockIdx.x * 256 + threadIdx.x) >> 5;
    int lane = threadIdx.x & 31;
    if (n >= NN) return;
    float c0 = 0.f, c1 = 0.f;
#pragma unroll
    for (int k = 0; k < 4; k++) {
        int idx = k * 32 + lane;
        float t = g_t2[n * F1 + idx];
        c0 = fmaf(t, W2[idx * 2 + 0], c0);
        c1 = fmaf(t, W2[idx * 2 + 1], c1);
    }
#pragma unroll
    for (int o = 16; o > 0; o >>= 1) {
        c0 += __shfl_xor_sync(0xFFFFFFFFu, c0, o);
        c1 += __shfl_xor_sync(0xFFFFFFFFu, c1, o);
    }
    if (lane == 0) {
        out[n * 2 + 0] = c0 + b2[0];
        out[n * 2 + 1] = c1 + b2[1];
    }
}

// ---------------- driver ---------------------------------------------------
extern "C" void kernel_launch(void* const* d_in, const int* in_sizes, int n_in,
                              void* d_out, int out_size)
{
    const float* x        = (const float*)d_in[0];
    const int*   edges    = (const int*)  d_in[1];
    const float* proj_W   = (const float*)d_in[2];
    const float* proj_b   = (const float*)d_in[3];
    const float* gat_W    = (const float*)d_in[4];
    const float* gat_asrc = (const float*)d_in[5];
    const float* gat_adst = (const float*)d_in[6];
    const float* gat_b    = (const float*)d_in[7];
    const float* sem_W1   = (const float*)d_in[8];
    const float* sem_b1   = (const float*)d_in[9];
    const float* sem_W2   = (const float*)d_in[10];
    const float* cls_W1   = (const float*)d_in[11];
    const float* cls_b1   = (const float*)d_in[12];
    const float* cls_W2   = (const float*)d_in[13];
    const float* cls_b2   = (const float*)d_in[14];
    float* out = (float*)d_out;

    float *h0, *hall, *hp, *emb, *t1, *t2, *z, *ssrc, *sdst;
    int *countp;
    __nv_bfloat16* wt;
    cudaGetSymbolAddress((void**)&h0,   g_h0);
    cudaGetSymbolAddress((void**)&hall, g_hall);
    cudaGetSymbolAddress((void**)&hp,   g_hp);
    cudaGetSymbolAddress((void**)&emb,  g_emb);
    cudaGetSymbolAddress((void**)&t1,   g_t1);
    cudaGetSymbolAddress((void**)&t2,   g_t2);
    cudaGetSymbolAddress((void**)&z,    g_z);
    cudaGetSymbolAddress((void**)&ssrc, g_ssrc);
    cudaGetSymbolAddress((void**)&sdst, g_sdst);
    cudaGetSymbolAddress((void**)&countp, g_count);
    cudaGetSymbolAddress((void**)&wt,     g_wt);

    const int SMEM = 66560;   // single-stage: occ 3 CTAs/SM
    cudaFuncSetAttribute(gemm_tc, cudaFuncAttributeMaxDynamicSharedMemorySize, SMEM);

    const int MT = NP / 128;                         // 391
    const int nodeWarpBlocks  = (NN + 7) / 8;
    const int allNodeWarpBlks = (PP * NN + 7) / 8;
    const int semWarpBlks     = (PP * NP + 7) / 8;
    const int allEdgeBlocks   = (PP * EE + 255) / 256;

    const long NPF = (long)NP * F;
    const long NP8 = (long)NP * Hh;

    // --- weight split/transposition ----------------------------------------
    conv_w_kernel<<<(128 * 256 + 255) / 256, 256>>>(proj_W, wt, wt + 32768, 128, 256);
    conv_w6_kernel<<<(6 * 65536 + 255) / 256, 256>>>(gat_W, wt + 65536);
    conv_w_kernel<<<(256 * 128 + 255) / 256, 256>>>(sem_W1, wt + 851968, wt + 884736, 256, 128);
    conv_w_kernel<<<(256 * 128 + 255) / 256, 256>>>(cls_W1, wt + 917504, wt + 950272, 256, 128);

    // --- CSR build ----------------------------------------------------------
    cudaMemsetAsync(countp, 0, sizeof(int) * PP * NN);
    csr_count_kernel<<<allEdgeBlocks, 256>>>(edges);
    csr_scan_kernel<<<1, 1024>>>();
    csr_scatter_kernel<<<allEdgeBlocks, 256>>>(edges);

    // h0 = x @ proj_W + proj_b   (M=NN guard; pad rows of h0 stay 0)
    gemm_tc<<<dim3(2, MT), 256, SMEM>>>(x, wt, wt + 32768, proj_b, h0,
                                        NN, 128, 256, 0,
                                        nullptr, nullptr, nullptr, nullptr,
                                        0, 0, 0, 0, 0, 0, 0);

    // --- layer 1 (all 3 metapaths in one launch each) -----------------------
    gemm_tc<<<dim3(6, MT), 256, SMEM>>>(h0, wt + 65536, wt + 131072, nullptr, hp,
                                        NP, 256, 256, 3,
                                        gat_asrc, gat_adst, ssrc, sdst,
                                        2, 0, 0, 262144, NPF, NP8, 512);
    gat_aggregate_all<<<allNodeWarpBlks, 256>>>(hp, ssrc, sdst, gat_b, hall);

    // --- layer 2 ------------------------------------------------------------
    gemm_tc<<<dim3(2, 3 * MT), 256, SMEM>>>(hall, wt + 65536 + 131072, wt + 65536 + 196608,
                                            nullptr, hp,
                                            NP, 256, 256, 3,
                                            gat_asrc + 256, gat_adst + 256, ssrc, sdst,
                                            0, MT, NPF, 262144, NPF, NP8, 512);
    gat_aggregate_all<<<allNodeWarpBlks, 256>>>(hp, ssrc, sdst, gat_b + 256, emb);

    // --- semantic attention (batched M = 3*NP) ------------------------------
    gemm_tc<<<dim3(1, 3 * MT), 256, SMEM>>>(emb, wt + 851968, wt + 884736, sem_b1, t1,
                                            3 * NP, 256, 128, 1,
                                            nullptr, nullptr, nullptr, nullptr,
                                            0, 0, 0, 0, 0, 0, 0);
    sem_score_kernel<<<semWarpBlks, 256>>>(sem_W2);
    sem_combine_kernel<<<nodeWarpBlocks, 256>>>();

    // --- classifier ---------------------------------------------------------
    gemm_tc<<<dim3(1, MT), 256, SMEM>>>(z, wt + 917504, wt + 950272, cls_b1, t2,
                                        NN, 256, 128, 2,
                                        nullptr, nullptr, nullptr, nullptr,
                                        0, 0, 0, 0, 0, 0, 0);
    cls_out_kernel<<<nodeWarpBlocks, 256>>>(cls_W2, cls_b2, out);
}

// round 17
// speedup vs baseline: 1.0410x; 1.0249x over previous
#include <cuda_runtime.h>
#include <cuda_bf16.h>
#include <math.h>
#include <stdint.h>
#include <string.h>

// Problem constants (fixed by the dataset)
constexpr int NN  = 50000;   // nodes
constexpr int NP  = 50048;   // nodes padded to 128 (391 tiles)
constexpr int F   = 256;     // hidden
constexpr int Hh  = 8;       // heads
constexpr int EE  = 800000;  // edges per metapath
constexpr int PP  = 3;       // metapaths
constexpr int F1  = 128;     // MLP hidden

// ---------------- scratch (device globals; zero-initialized) ---------------
__device__ __align__(16) float g_h0 [NP * F];           // pad rows stay 0
__device__ __align__(16) float g_h  [NP * F];
__device__ __align__(16) float g_hp [NP * F];           // per-path, L2-resident
__device__ __align__(16) float g_ssrc[NP * Hh];
__device__ __align__(16) float g_sdst[NP * Hh];
__device__ __align__(16) float g_emb [PP * NP * F];     // pad rows stay 0
__device__ __align__(16) float g_t1  [PP * NP * F1];
__device__ __align__(16) float g_sc  [NN * PP];
__device__ __align__(16) float g_z   [NN * F];
__device__ __align__(16) float g_t2  [NN * F1];

// CSR structures
__device__ int g_count [PP * NN];
__device__ int g_indptr[PP * (NN + 1)];
__device__ int g_cursor[PP * NN];
__device__ int g_csrc  [PP * EE];

// split-bf16 weights, transposed to [N][K], hi then lo per matrix
__device__ __align__(16) __nv_bfloat16 g_wt[983040];

// feature gate: tcgen05 only exists in an arch-specific (sm_103a/100a) pass
#if defined(__CUDA_ARCH_FEAT_SM103_ALL) || defined(__CUDA_ARCH_FEAT_SM100_ALL) || defined(__CUDA_ARCH_FEAT_SM101_ALL)
#define HAVE_TCGEN05 1
#else
#define HAVE_TCGEN05 0
#endif

// ---------------- PTX helpers ----------------------------------------------
__device__ __forceinline__ uint32_t elect_one_pred() {
    uint32_t pred;
    asm volatile(
        "{\n\t.reg .pred p;\n\t"
        "elect.sync _|p, 0xFFFFFFFF;\n\t"
        "selp.b32 %0, 1, 0, p;\n\t}"
        : "=r"(pred));
    return pred;
}
__device__ __forceinline__ uint32_t smem_u32(const void* p) {
    uint32_t a;
    asm("{ .reg .u64 t; cvta.to.shared.u64 t, %1; cvt.u32.u64 %0, t; }"
        : "=r"(a) : "l"(p));
    return a;
}

static constexpr uint64_t SMEM_DESC_BASE_SW128 =
    (uint64_t(2)  << 61) | (uint64_t(1) << 46) | (uint64_t(64) << 32) | (uint64_t(1) << 16);

__device__ __forceinline__ uint64_t make_desc(uint32_t addr) {
    return SMEM_DESC_BASE_SW128 | ((uint64_t)(addr >> 4) & 0x3FFF);
}

#if HAVE_TCGEN05
__device__ __forceinline__ void tc_alloc(uint32_t smem_dst, uint32_t ncols) {
    asm volatile("tcgen05.alloc.cta_group::1.sync.aligned.shared::cta.b32 [%0], %1;"
                 :: "r"(smem_dst), "r"(ncols) : "memory");
}
__device__ __forceinline__ void tc_relinquish() {
    asm volatile("tcgen05.relinquish_alloc_permit.cta_group::1.sync.aligned;");
}
__device__ __forceinline__ void tc_dealloc(uint32_t tmem, uint32_t ncols) {
    asm volatile("tcgen05.dealloc.cta_group::1.sync.aligned.b32 %0, %1;"
                 :: "r"(tmem), "r"(ncols));
}
__device__ __forceinline__ void mbar_init(uint32_t mbar, uint32_t cnt) {
    asm volatile("mbarrier.init.shared.b64 [%0], %1;" :: "r"(mbar), "r"(cnt) : "memory");
}
__device__ __forceinline__ void mbar_inval(uint32_t mbar) {
    asm volatile("mbarrier.inval.shared.b64 [%0];" :: "r"(mbar) : "memory");
}
__device__ __forceinline__ void mbar_wait(uint32_t mbar, uint32_t parity) {
    asm volatile(
        "{\n\t.reg .pred P;\n"
        "W_%=:\n\t"
        "mbarrier.try_wait.parity.acquire.cta.shared::cta.b64 P, [%0], %1, 0x989680;\n\t"
        "@P bra.uni D_%=;\n\t"
        "bra.uni W_%=;\n"
        "D_%=:\n\t}"
        :: "r"(mbar), "r"(parity) : "memory");
}
__device__ __forceinline__ void tc_commit(uint32_t mbar) {
    asm volatile("tcgen05.commit.cta_group::1.mbarrier::arrive::one.shared::cluster.b64 [%0];"
                 :: "r"(mbar) : "memory");
}
__device__ __forceinline__ void tc_mma_bf16_ss(uint32_t d, uint64_t ad, uint64_t bd,
                                               uint32_t idesc, uint32_t en) {
    asm volatile(
        "{\n\t.reg .pred p;\n\t"
        "setp.ne.u32 p, %5, 0;\n\t"
        "tcgen05.mma.cta_group::1.kind::f16 [%0], %1, %2, %3, {%4, %4, %4, %4}, p;\n\t}"
        :: "r"(d), "l"(ad), "l"(bd), "r"(idesc), "r"(0u), "r"(en)
        : "memory");
}
#define TC_LD_32X32B_X32(r, addr) \
    asm volatile( \
        "tcgen05.ld.sync.aligned.32x32b.x32.b32 " \
        "{%0, %1, %2, %3, %4, %5, %6, %7, " \
        " %8, %9, %10, %11, %12, %13, %14, %15, " \
        " %16, %17, %18, %19, %20, %21, %22, %23, " \
        " %24, %25, %26, %27, %28, %29, %30, %31}, [%32];" \
        : "=r"((r)[0]),  "=r"((r)[1]),  "=r"((r)[2]),  "=r"((r)[3]), \
          "=r"((r)[4]),  "=r"((r)[5]),  "=r"((r)[6]),  "=r"((r)[7]), \
          "=r"((r)[8]),  "=r"((r)[9]),  "=r"((r)[10]), "=r"((r)[11]), \
          "=r"((r)[12]), "=r"((r)[13]), "=r"((r)[14]), "=r"((r)[15]), \
          "=r"((r)[16]), "=r"((r)[17]), "=r"((r)[18]), "=r"((r)[19]), \
          "=r"((r)[20]), "=r"((r)[21]), "=r"((r)[22]), "=r"((r)[23]), \
          "=r"((r)[24]), "=r"((r)[25]), "=r"((r)[26]), "=r"((r)[27]), \
          "=r"((r)[28]), "=r"((r)[29]), "=r"((r)[30]), "=r"((r)[31]) \
        : "r"(addr))
#endif  // HAVE_TCGEN05

__device__ __forceinline__ uint32_t pack2(__nv_bfloat16 a, __nv_bfloat16 b) {
    __nv_bfloat162 t; t.x = a; t.y = b;
    uint32_t u; memcpy(&u, &t, 4); return u;
}

// ---------------- weight conversion: W[K][N] fp32 -> Wt_hi/lo [N][K] bf16 --
__global__ __launch_bounds__(256)
void conv_w_kernel(const float* __restrict__ src, __nv_bfloat16* __restrict__ hi,
                   __nv_bfloat16* __restrict__ lo, int K, int N)
{
    int idx = blockIdx.x * 256 + threadIdx.x;
    if (idx >= K * N) return;
    int k = idx / N, n = idx - k * N;
    float v = src[idx];
    __nv_bfloat16 h = __float2bfloat16(v);
    float l = v - __bfloat162float(h);
    hi[(size_t)n * K + k] = h;
    lo[(size_t)n * K + k] = __float2bfloat16(l);
}

// all 6 GAT weight matrices (256x256) in one launch
__global__ __launch_bounds__(256)
void conv_w6_kernel(const float* __restrict__ src, __nv_bfloat16* __restrict__ dst)
{
    int idx = blockIdx.x * 256 + threadIdx.x;        // 6*65536 total
    int li  = idx >> 16;
    int rem = idx & 65535;
    int k = rem >> 8, n = rem & 255;
    float v = src[(size_t)li * 65536 + rem];
    __nv_bfloat16 h = __float2bfloat16(v);
    float l = v - __bfloat162float(h);
    __nv_bfloat16* base = dst + (size_t)li * 131072;
    base[n * 256 + k]         = h;
    base[65536 + n * 256 + k] = __float2bfloat16(l);
}

// ---------------- GEMM: single-stage tcgen05 (occ 3) + FFMA fallback --------
// C = act(A[M,K] @ W[K,N] + bias); W split-bf16 transposed [N][K].
// act: 0 none, 1 tanh, 2 relu, 3 GAT (no bias; emit per-head ssrc/sdst).
// grid: (N/128, ceil(M/128)); 256 threads; dynamic smem 66560 B.
__global__ __launch_bounds__(256)
void gemm_tc(const float* __restrict__ A, const __nv_bfloat16* __restrict__ Bhi,
             const __nv_bfloat16* __restrict__ Blo, const float* __restrict__ bias,
             float* __restrict__ C, int M, int K, int N, int act,
             const float* __restrict__ asrc, const float* __restrict__ adst,
             float* __restrict__ ssrc, float* __restrict__ sdst)
{
    extern __shared__ char smem[];
    const int tid  = threadIdx.x;
    const int wid  = tid >> 5;
    const int lane = tid & 31;
    const int m0   = blockIdx.y * 128;
    const int c0   = blockIdx.x * 128;

#if HAVE_TCGEN05
    const uint32_t sb = smem_u32(smem);
    const int SM_AHI = 1024;
    const int SM_ALO = 1024 + 16384;
    const int SM_BHI = 1024 + 32768;
    const int SM_BLO = 1024 + 49152;

    if (wid == 0) { tc_alloc(sb, 128u); tc_relinquish(); }
    if (tid == 0) { mbar_init(sb + 8, 1); }
    __syncthreads();
    uint32_t tmem;
    asm volatile("ld.shared.b32 %0, [%1];" : "=r"(tmem) : "r"(sb));

    const uint32_t idesc = 0x490u | (16u << 17) | (8u << 24);  // bf16, M128, N128
    const int nchunks = K >> 6;

    for (int ch = 0; ch < nchunks; ch++) {
        const int k0 = ch << 6;
        // A tile: fp32 -> bf16 hi/lo, SW128 [128 rows x 64 k]
        {
            const int r  = tid >> 1;
            const int cb = (tid & 1) * 32;
            const int gr = m0 + r;
            const bool vr = gr < M;
            const float* ap = A + (size_t)gr * K + k0 + cb;
#pragma unroll
            for (int j = 0; j < 8; j++) {
                float4 v = vr ? *(const float4*)(ap + j * 4)
                              : make_float4(0.f, 0.f, 0.f, 0.f);
                __nv_bfloat16 hx = __float2bfloat16(v.x);
                __nv_bfloat16 hy = __float2bfloat16(v.y);
                __nv_bfloat16 hz = __float2bfloat16(v.z);
                __nv_bfloat16 hw = __float2bfloat16(v.w);
                __nv_bfloat16 lx = __float2bfloat16(v.x - __bfloat162float(hx));
                __nv_bfloat16 ly = __float2bfloat16(v.y - __bfloat162float(hy));
                __nv_bfloat16 lz = __float2bfloat16(v.z - __bfloat162float(hz));
                __nv_bfloat16 lw = __float2bfloat16(v.w - __bfloat162float(hw));
                uint32_t byte = (uint32_t)(r * 128 + (cb + j * 4) * 2);
                uint32_t sw   = byte ^ ((byte >> 3) & 0x70);
                *(uint2*)(smem + SM_AHI + sw) = make_uint2(pack2(hx, hy), pack2(hz, hw));
                *(uint2*)(smem + SM_ALO + sw) = make_uint2(pack2(lx, ly), pack2(lz, lw));
            }
        }
        // B tiles: 128 n-rows x 64 k bf16, SW128, from [N][K] gmem
        {
#pragma unroll
            for (int it = 0; it < 4; it++) {
                int idx = it * 256 + tid;
                int n  = idx >> 3;
                int kp = idx & 7;
                uint32_t byte = (uint32_t)(n * 128 + kp * 16);
                uint32_t sw   = byte ^ ((byte >> 3) & 0x70);
                const size_t go = (size_t)(c0 + n) * K + k0 + kp * 8;
                *(uint4*)(smem + SM_BHI + sw) = *(const uint4*)(Bhi + go);
                *(uint4*)(smem + SM_BLO + sw) = *(const uint4*)(Blo + go);
            }
        }
        __syncthreads();

        if (wid == 0) {
            asm volatile("fence.proxy.async.shared::cta;" ::: "memory");
            if (elect_one_pred()) {
                uint64_t ah = make_desc(sb + SM_AHI);
                uint64_t al = make_desc(sb + SM_ALO);
                uint64_t bh = make_desc(sb + SM_BHI);
                uint64_t bl = make_desc(sb + SM_BLO);
#pragma unroll
                for (int ks = 0; ks < 4; ks++)
                    tc_mma_bf16_ss(tmem, ah + 2 * ks, bh + 2 * ks, idesc,
                                   (ch == 0 && ks == 0) ? 0u : 1u);
#pragma unroll
                for (int ks = 0; ks < 4; ks++)
                    tc_mma_bf16_ss(tmem, ah + 2 * ks, bl + 2 * ks, idesc, 1u);
#pragma unroll
                for (int ks = 0; ks < 4; ks++)
                    tc_mma_bf16_ss(tmem, al + 2 * ks, bh + 2 * ks, idesc, 1u);
                tc_commit(sb + 8);
            }
        }
        mbar_wait(sb + 8, (uint32_t)(ch & 1));
    }

    asm volatile("tcgen05.fence::after_thread_sync;" ::: "memory");

    if (wid < 4) {
        const int m = m0 + wid * 32 + lane;
        const bool valid = m < M;
        for (int cb = 0; cb < 4; cb++) {
            uint32_t r[32];
            TC_LD_32X32B_X32(r, tmem + cb * 32);
            asm volatile("tcgen05.wait::ld.sync.aligned;" ::: "memory");
            if (valid) {
                float* cp = C + (size_t)m * N + c0 + cb * 32;
                if (act == 3) {
                    float ss = 0.f, sd = 0.f;
#pragma unroll
                    for (int c = 0; c < 32; c += 4) {
                        float v0 = __uint_as_float(r[c + 0]);
                        float v1 = __uint_as_float(r[c + 1]);
                        float v2 = __uint_as_float(r[c + 2]);
                        float v3 = __uint_as_float(r[c + 3]);
                        int col = c0 + cb * 32 + c;
                        ss = fmaf(v0, asrc[col + 0], ss); sd = fmaf(v0, adst[col + 0], sd);
                        ss = fmaf(v1, asrc[col + 1], ss); sd = fmaf(v1, adst[col + 1], sd);
                        ss = fmaf(v2, asrc[col + 2], ss); sd = fmaf(v2, adst[col + 2], sd);
                        ss = fmaf(v3, asrc[col + 3], ss); sd = fmaf(v3, adst[col + 3], sd);
                        *(float4*)(cp + c) = make_float4(v0, v1, v2, v3);
                    }
                    int head = (c0 >> 5) + cb;
                    ssrc[m * 8 + head] = ss;
                    sdst[m * 8 + head] = sd;
                } else {
#pragma unroll
                    for (int c = 0; c < 32; c += 4) {
                        int col = c0 + cb * 32 + c;
                        float v0 = __uint_as_float(r[c + 0]) + (bias ? bias[col + 0] : 0.f);
                        float v1 = __uint_as_float(r[c + 1]) + (bias ? bias[col + 1] : 0.f);
                        float v2 = __uint_as_float(r[c + 2]) + (bias ? bias[col + 2] : 0.f);
                        float v3 = __uint_as_float(r[c + 3]) + (bias ? bias[col + 3] : 0.f);
                        if (act == 1) {
                            v0 = tanhf(v0); v1 = tanhf(v1); v2 = tanhf(v2); v3 = tanhf(v3);
                        } else if (act == 2) {
                            v0 = fmaxf(v0, 0.f); v1 = fmaxf(v1, 0.f);
                            v2 = fmaxf(v2, 0.f); v3 = fmaxf(v3, 0.f);
                        }
                        *(float4*)(cp + c) = make_float4(v0, v1, v2, v3);
                    }
                }
            }
        }
        asm volatile("tcgen05.fence::before_thread_sync;" ::: "memory");
    }

    __syncthreads();
    if (wid == 0) {
        if (elect_one_pred()) mbar_inval(sb + 8);
        tc_dealloc(tmem, 128u);
    }

#else
    // =================== FFMA fallback (baseline sm_103) ===================
    float (*As)[128] = (float(*)[128])(smem);            //  8 KB
    float (*Bs)[128] = (float(*)[128])(smem + 8192);     //  8 KB
    float* sred_s = (float*)(smem + 16384);              //  2 KB [128][4]
    float* sred_d = (float*)(smem + 18432);              //  2 KB

    const int tx = tid & 15;
    const int ty = tid >> 4;

    float acc[8][8];
#pragma unroll
    for (int i = 0; i < 8; i++)
#pragma unroll
        for (int j = 0; j < 8; j++) acc[i][j] = 0.f;

    const int ar = tid >> 1;
    const int ac = (tid & 1) * 8;
    const int nl = tid >> 1;
    const int kb = (tid & 1) * 8;

    for (int k0 = 0; k0 < K; k0 += 16) {
        {
            int gr = m0 + ar;
            float4 a0, a1;
            if (gr < M) {
                const float* ap = A + (size_t)gr * K + k0 + ac;
                a0 = *(const float4*)(ap);
                a1 = *(const float4*)(ap + 4);
            } else {
                a0 = make_float4(0.f, 0.f, 0.f, 0.f);
                a1 = a0;
            }
            As[ac + 0][ar] = a0.x; As[ac + 1][ar] = a0.y;
            As[ac + 2][ar] = a0.z; As[ac + 3][ar] = a0.w;
            As[ac + 4][ar] = a1.x; As[ac + 5][ar] = a1.y;
            As[ac + 6][ar] = a1.z; As[ac + 7][ar] = a1.w;
        }
        {
            const size_t go = (size_t)(c0 + nl) * K + k0 + kb;
            uint4 vh = *(const uint4*)(Bhi + go);
            uint4 vl = *(const uint4*)(Blo + go);
            const __nv_bfloat16* hb = (const __nv_bfloat16*)&vh;
            const __nv_bfloat16* lb = (const __nv_bfloat16*)&vl;
#pragma unroll
            for (int j = 0; j < 8; j++)
                Bs[kb + j][nl] = __bfloat162float(hb[j]) + __bfloat162float(lb[j]);
        }
        __syncthreads();
#pragma unroll
        for (int kk = 0; kk < 16; kk++) {
            float a[8], b[8];
            *(float4*)(a)     = *(float4*)&As[kk][ty * 8];
            *(float4*)(a + 4) = *(float4*)&As[kk][ty * 8 + 4];
            *(float4*)(b)     = *(float4*)&Bs[kk][tx * 8];
            *(float4*)(b + 4) = *(float4*)&Bs[kk][tx * 8 + 4];
#pragma unroll
            for (int i = 0; i < 8; i++)
#pragma unroll
                for (int j = 0; j < 8; j++) acc[i][j] = fmaf(a[i], b[j], acc[i][j]);
        }
        __syncthreads();
    }

    const int row0 = m0 + ty * 8;
    const int colg = c0 + tx * 8;

    if (act == 3) {
        for (int idx = tid; idx < 1024; idx += 256) ((float*)(smem + 16384))[idx] = 0.f;
        __syncthreads();
        const int hb = tx >> 2;   // head within block (0..3)
#pragma unroll
        for (int i = 0; i < 8; i++) {
            int r = row0 + i;
            if (r >= M) break;
            float ss = 0.f, sd = 0.f;
            float* cp = C + (size_t)r * N + colg;
#pragma unroll
            for (int j = 0; j < 8; j++) {
                float v = acc[i][j];
                ss = fmaf(v, asrc[colg + j], ss);
                sd = fmaf(v, adst[colg + j], sd);
                cp[j] = v;
            }
            atomicAdd(&sred_s[(ty * 8 + i) * 4 + hb], ss);
            atomicAdd(&sred_d[(ty * 8 + i) * 4 + hb], sd);
        }
        __syncthreads();
        for (int idx = tid; idx < 512; idx += 256) {
            int r = idx >> 2, h = idx & 3;
            int m = m0 + r;
            if (m < M) {
                int head = (c0 >> 5) + h;
                ssrc[m * 8 + head] = sred_s[idx];
                sdst[m * 8 + head] = sred_d[idx];
            }
        }
    } else {
        float bv[8];
#pragma unroll
        for (int j = 0; j < 8; j++) bv[j] = bias ? bias[colg + j] : 0.f;
#pragma unroll
        for (int i = 0; i < 8; i++) {
            int r = row0 + i;
            if (r >= M) break;
            float* cp = C + (size_t)r * N + colg;
#pragma unroll
            for (int j = 0; j < 8; j++) {
                float v = acc[i][j] + bv[j];
                if (act == 1)      v = tanhf(v);
                else if (act == 2) v = fmaxf(v, 0.f);
                cp[j] = v;
            }
        }
    }
#endif
}

// ---------------- CSR build ------------------------------------------------
__global__ __launch_bounds__(256)
void csr_count_kernel(const int* __restrict__ edges)
{
    int idx = blockIdx.x * 256 + threadIdx.x;
    if (idx >= PP * EE) return;
    int p = idx / EE, e = idx - p * EE;
    int d = edges[(size_t)p * 2 * EE + EE + e];
    atomicAdd(&g_count[p * NN + d], 1);
}

__global__ __launch_bounds__(1024)
void csr_scan_kernel()
{
    __shared__ int warp_off[32];
    __shared__ int s_carry;
    const int lane = threadIdx.x & 31;
    const int wid  = threadIdx.x >> 5;

    for (int p = 0; p < PP; p++) {
        const int* counts = g_count  + p * NN;
        int*       indptr = g_indptr + p * (NN + 1);
        int*       cursor = g_cursor + p * NN;
        if (threadIdx.x == 0) s_carry = 0;
        __syncthreads();
        for (int base = 0; base < NN; base += 1024) {
            int i = base + (int)threadIdx.x;
            int v = (i < NN) ? counts[i] : 0;
            int incl = v;
#pragma unroll
            for (int o = 1; o < 32; o <<= 1) {
                int t = __shfl_up_sync(0xFFFFFFFFu, incl, o);
                if (lane >= o) incl += t;
            }
            if (lane == 31) warp_off[wid] = incl;
            __syncthreads();
            if (wid == 0) {
                int ws = warp_off[lane];
                int wincl = ws;
#pragma unroll
                for (int o = 1; o < 32; o <<= 1) {
                    int t = __shfl_up_sync(0xFFFFFFFFu, wincl, o);
                    if (lane >= o) wincl += t;
                }
                warp_off[lane] = wincl - ws;
            }
            __syncthreads();
            int excl = incl - v + warp_off[wid] + s_carry;
            if (i < NN) { indptr[i] = excl; cursor[i] = excl; }
            __syncthreads();
            if (threadIdx.x == 1023) s_carry = excl + v;
            __syncthreads();
        }
        if (threadIdx.x == 0) indptr[NN] = s_carry;
        __syncthreads();
    }
}

__global__ __launch_bounds__(256)
void csr_scatter_kernel(const int* __restrict__ edges)
{
    int idx = blockIdx.x * 256 + threadIdx.x;
    if (idx >= PP * EE) return;
    int p = idx / EE, e = idx - p * EE;
    int s = edges[(size_t)p * 2 * EE + e];
    int d = edges[(size_t)p * 2 * EE + EE + e];
    int pos = atomicAdd(&g_cursor[p * NN + d], 1);
    g_csrc[(size_t)p * EE + pos] = s;
}

__device__ __forceinline__ float leaky02(float v) { return (v > 0.f) ? v : 0.2f * v; }

// ---------------- fused CSR aggregate (per path, hp L2-resident) -----------
__global__ __launch_bounds__(256)
void gat_aggregate_kernel(const int* __restrict__ indptr, const int* __restrict__ csrc,
                          const float* __restrict__ bias, float* __restrict__ out)
{
    int n    = (blockIdx.x * 256 + threadIdx.x) >> 5;
    int lane = threadIdx.x & 31;
    if (n >= NN) return;

    const int beg = indptr[n];
    const int end = indptr[n + 1];

    float sd = 0.f, eself = 0.f;
    if (lane < 8) {
        sd    = g_sdst[n * 8 + lane];
        eself = leaky02(g_ssrc[n * 8 + lane] + sd);
    }
    // pass 1: per-head max
    float m = eself;
    for (int ptr = beg; ptr < end; ptr++) {
        int s = csrc[ptr];
        if (lane < 8)
            m = fmaxf(m, leaky02(g_ssrc[s * 8 + lane] + sd));
    }

    // pass 2: exp-weighted gather accumulate (unrolled by 2)
    float den = (lane < 8) ? __expf(eself - m) : 0.f;
    const float exself = den;
    float accv[8];
#pragma unroll
    for (int k = 0; k < 8; k++) accv[k] = 0.f;

    int ptr = beg;
    for (; ptr + 2 <= end; ptr += 2) {
        int s0 = csrc[ptr], s1 = csrc[ptr + 1];
        float ex0 = 0.f, ex1 = 0.f;
        if (lane < 8) {
            ex0 = __expf(leaky02(g_ssrc[s0 * 8 + lane] + sd) - m);
            ex1 = __expf(leaky02(g_ssrc[s1 * 8 + lane] + sd) - m);
            den += ex0 + ex1;
        }
        float e0h[8], e1h[8];
#pragma unroll
        for (int k = 0; k < 8; k++) {
            e0h[k] = __shfl_sync(0xFFFFFFFFu, ex0, k);
            e1h[k] = __shfl_sync(0xFFFFFFFFu, ex1, k);
        }
        const float* h0p = g_hp + (size_t)s0 * F;
        const float* h1p = g_hp + (size_t)s1 * F;
#pragma unroll
        for (int k = 0; k < 8; k++)
            accv[k] = fmaf(e0h[k], h0p[k * 32 + lane], accv[k]);
#pragma unroll
        for (int k = 0; k < 8; k++)
            accv[k] = fmaf(e1h[k], h1p[k * 32 + lane], accv[k]);
    }
    if (ptr < end) {
        int s = csrc[ptr];
        float ex = 0.f;
        if (lane < 8) {
            ex = __expf(leaky02(g_ssrc[s * 8 + lane] + sd) - m);
            den += ex;
        }
        float exh[8];
#pragma unroll
        for (int k = 0; k < 8; k++) exh[k] = __shfl_sync(0xFFFFFFFFu, ex, k);
        const float* hsp = g_hp + (size_t)s * F;
#pragma unroll
        for (int k = 0; k < 8; k++)
            accv[k] = fmaf(exh[k], hsp[k * 32 + lane], accv[k]);
    }

    float exsh[8], dh[8];
#pragma unroll
    for (int k = 0; k < 8; k++) {
        exsh[k] = __shfl_sync(0xFFFFFFFFu, exself, k);
        dh[k]   = __shfl_sync(0xFFFFFFFFu, den, k);
    }
    const float* hpn = g_hp + (size_t)n * F;
    float*       op  = out  + (size_t)n * F;
#pragma unroll
    for (int k = 0; k < 8; k++) {
        int idx = k * 32 + lane;
        float v = (accv[k] + exsh[k] * hpn[idx]) / dh[k] + bias[idx];
        v = (v > 0.f) ? v : expm1f(v);   // ELU(alpha=1)
        op[idx] = v;
    }
}

// ---------------- semantic score (batched over all paths) ------------------
__global__ __launch_bounds__(256)
void sem_score_kernel(const float* __restrict__ W2)
{
    int gw   = (blockIdx.x * 256 + threadIdx.x) >> 5;
    int lane = threadIdx.x & 31;
    if (gw >= PP * NP) return;
    int p = gw / NP;
    int n = gw - p * NP;
    if (n >= NN) return;
    float ssum = 0.f;
#pragma unroll
    for (int k = 0; k < 4; k++) {
        int idx = k * 32 + lane;
        ssum = fmaf(g_t1[(size_t)gw * F1 + idx], W2[idx], ssum);
    }
#pragma unroll
    for (int o = 16; o > 0; o >>= 1) ssum += __shfl_xor_sync(0xFFFFFFFFu, ssum, o);
    if (lane == 0) g_sc[n * PP + p] = ssum;
}

// ---------------- semantic softmax + weighted combine ----------------------
__global__ __launch_bounds__(256)
void sem_combine_kernel()
{
    int n    = (blockIdx.x * 256 + threadIdx.x) >> 5;
    int lane = threadIdx.x & 31;
    if (n >= NN) return;
    float s0 = g_sc[n * PP + 0], s1 = g_sc[n * PP + 1], s2 = g_sc[n * PP + 2];
    float mx = fmaxf(s0, fmaxf(s1, s2));
    float w0 = __expf(s0 - mx), w1 = __expf(s1 - mx), w2 = __expf(s2 - mx);
    float inv = 1.f / (w0 + w1 + w2);
    w0 *= inv; w1 *= inv; w2 *= inv;
    const float* e0 = g_emb + (size_t)n * F;
    const float* e1 = g_emb + ((size_t)NP + n) * F;
    const float* e2 = g_emb + ((size_t)2 * NP + n) * F;
    float* zp = g_z + (size_t)n * F;
#pragma unroll
    for (int k = 0; k < 8; k++) {
        int idx = k * 32 + lane;
        zp[idx] = w0 * e0[idx] + w1 * e1[idx] + w2 * e2[idx];
    }
}

// ---------------- classifier head: logits = t2 @ W2 + b2 -------------------
__global__ __launch_bounds__(256)
void cls_out_kernel(const float* __restrict__ W2, const float* __restrict__ b2,
                    float* __restrict__ out)
{
    int n    = (blockIdx.x * 256 + threadIdx.x) >> 5;
    int lane = threadIdx.x & 31;
    if (n >= NN) return;
    float c0 = 0.f, c1 = 0.f;
#pragma unroll
    for (int k = 0; k < 4; k++) {
        int idx = k * 32 + lane;
        float t = g_t2[n * F1 + idx];
        c0 = fmaf(t, W2[idx * 2 + 0], c0);
        c1 = fmaf(t, W2[idx * 2 + 1], c1);
    }
#pragma unroll
    for (int o = 16; o > 0; o >>= 1) {
        c0 += __shfl_xor_sync(0xFFFFFFFFu, c0, o);
        c1 += __shfl_xor_sync(0xFFFFFFFFu, c1, o);
    }
    if (lane == 0) {
        out[n * 2 + 0] = c0 + b2[0];
        out[n * 2 + 1] = c1 + b2[1];
    }
}

// ---------------- driver ---------------------------------------------------
extern "C" void kernel_launch(void* const* d_in, const int* in_sizes, int n_in,
                              void* d_out, int out_size)
{
    const float* x        = (const float*)d_in[0];
    const int*   edges    = (const int*)  d_in[1];
    const float* proj_W   = (const float*)d_in[2];
    const float* proj_b   = (const float*)d_in[3];
    const float* gat_W    = (const float*)d_in[4];
    const float* gat_asrc = (const float*)d_in[5];
    const float* gat_adst = (const float*)d_in[6];
    const float* gat_b    = (const float*)d_in[7];
    const float* sem_W1   = (const float*)d_in[8];
    const float* sem_b1   = (const float*)d_in[9];
    const float* sem_W2   = (const float*)d_in[10];
    const float* cls_W1   = (const float*)d_in[11];
    const float* cls_b1   = (const float*)d_in[12];
    const float* cls_W2   = (const float*)d_in[13];
    const float* cls_b2   = (const float*)d_in[14];
    float* out = (float*)d_out;

    float *h0, *h, *hp, *emb, *t1, *t2, *z, *ssrc, *sdst;
    int *countp, *indptr, *csrc;
    __nv_bfloat16* wt;
    cudaGetSymbolAddress((void**)&h0,  g_h0);
    cudaGetSymbolAddress((void**)&h,   g_h);
    cudaGetSymbolAddress((void**)&hp,  g_hp);
    cudaGetSymbolAddress((void**)&emb, g_emb);
    cudaGetSymbolAddress((void**)&t1,  g_t1);
    cudaGetSymbolAddress((void**)&t2,  g_t2);
    cudaGetSymbolAddress((void**)&z,   g_z);
    cudaGetSymbolAddress((void**)&ssrc, g_ssrc);
    cudaGetSymbolAddress((void**)&sdst, g_sdst);
    cudaGetSymbolAddress((void**)&countp, g_count);
    cudaGetSymbolAddress((void**)&indptr, g_indptr);
    cudaGetSymbolAddress((void**)&csrc,   g_csrc);
    cudaGetSymbolAddress((void**)&wt,     g_wt);

    const int SMEM = 66560;   // single-stage: occ 3 CTAs/SM
    cudaFuncSetAttribute(gemm_tc, cudaFuncAttributeMaxDynamicSharedMemorySize, SMEM);

    const int MT = NP / 128;                         // 391
    const int nodeWarpBlocks = (NN + 7) / 8;
    const int semWarpBlks    = (PP * NP + 7) / 8;
    const int allEdgeBlocks  = (PP * EE + 255) / 256;

    // --- weight split/transposition ----------------------------------------
    conv_w_kernel<<<(128 * 256 + 255) / 256, 256>>>(proj_W, wt, wt + 32768, 128, 256);
    conv_w6_kernel<<<(6 * 65536 + 255) / 256, 256>>>(gat_W, wt + 65536);
    conv_w_kernel<<<(256 * 128 + 255) / 256, 256>>>(sem_W1, wt + 851968, wt + 884736, 256, 128);
    conv_w_kernel<<<(256 * 128 + 255) / 256, 256>>>(cls_W1, wt + 917504, wt + 950272, 256, 128);

    // --- CSR build ----------------------------------------------------------
    cudaMemsetAsync(countp, 0, sizeof(int) * PP * NN);
    csr_count_kernel<<<allEdgeBlocks, 256>>>(edges);
    csr_scan_kernel<<<1, 1024>>>();
    csr_scatter_kernel<<<allEdgeBlocks, 256>>>(edges);

    // h0 = x @ proj_W + proj_b
    gemm_tc<<<dim3(2, MT), 256, SMEM>>>(x, wt, wt + 32768, proj_b, h0,
                                        NN, 128, 256, 0, nullptr, nullptr, nullptr, nullptr);

    // --- sequential per-path chains: hp stays 51 MB, L2-resident ------------
    for (int p = 0; p < PP; p++) {
        const int* ip = indptr + (size_t)p * (NN + 1);
        const int* cs = csrc   + (size_t)p * EE;
        const float* hin = h0;
        for (int l = 0; l < 2; l++) {
            int li = p * 2 + l;
            __nv_bfloat16* wb = wt + 65536 + (size_t)li * 131072;
            const float* as = gat_asrc + (size_t)li * 256;
            const float* ad = gat_adst + (size_t)li * 256;
            const float* bb = gat_b    + (size_t)li * 256;

            gemm_tc<<<dim3(2, MT), 256, SMEM>>>(hin, wb, wb + 65536, nullptr, hp,
                                                NN, 256, 256, 3, as, ad, ssrc, sdst);
            float* obuf = (l == 0) ? h : (emb + (size_t)p * NP * F);
            gat_aggregate_kernel<<<nodeWarpBlocks, 256>>>(ip, cs, bb, obuf);
            hin = h;
        }
    }

    // --- semantic attention (batched M = 3*NP; emb pad rows are 0) ----------
    gemm_tc<<<dim3(1, 3 * MT), 256, SMEM>>>(emb, wt + 851968, wt + 884736, sem_b1, t1,
                                            3 * NP, 256, 128, 1,
                                            nullptr, nullptr, nullptr, nullptr);
    sem_score_kernel<<<semWarpBlks, 256>>>(sem_W2);
    sem_combine_kernel<<<nodeWarpBlocks, 256>>>();

    // --- classifier ---------------------------------------------------------
    gemm_tc<<<dim3(1, MT), 256, SMEM>>>(z, wt + 917504, wt + 950272, cls_b1, t2,
                                        NN, 256, 128, 2,
                                        nullptr, nullptr, nullptr, nullptr);
    cls_out_kernel<<<nodeWarpBlocks, 256>>>(cls_W2, cls_b2, out);
}